// round 6
// baseline (speedup 1.0000x reference)
#include <cuda_runtime.h>

#define NN 10000
#define NE 160000
#define FD 128
#define F8 1024
#define NRB 32

// phi buffer [NN, 8F] = 40 MB (static device scratch; no allocation)
__device__ float g_phi[(size_t)NN * F8];

// ---------------------------------------------------------------------------
// phi = silu(s @ W1 + b1) @ W2 + b2          (fp32 FFMA, smem-tiled)
// Block: 256 threads, BM=32 rows of s/phi. smem: A[32][128] + B[128][128].
// ---------------------------------------------------------------------------
#define PHI_BM 32
#define PHI_SMEM ((PHI_BM * FD + FD * FD) * 4)

__global__ __launch_bounds__(256) void phi_kernel(
    const float* __restrict__ s,
    const float* __restrict__ W1, const float* __restrict__ b1,
    const float* __restrict__ W2, const float* __restrict__ b2)
{
    extern __shared__ float sm[];
    float* A = sm;                 // [PHI_BM][FD]  s tile, then h tile
    float* B = sm + PHI_BM * FD;   // [FD][FD]      W1, then W2 chunks

    const int t = threadIdx.x;
    const int row0 = blockIdx.x * PHI_BM;
    const int tx = t & 31;         // column group: cols c = tx*4 .. tx*4+3
    const int ty = t >> 5;         // row group:    rows r = ty*4 .. ty*4+3

    // ---- load s tile (guarded) ----
    {
        const float4* s4 = (const float4*)s;
        #pragma unroll
        for (int i = 0; i < 4; i++) {
            int idx = t + 256 * i;             // f4 idx in [0,1024): row=idx>>5, col4=idx&31
            int r = idx >> 5;
            float4 val = make_float4(0.f, 0.f, 0.f, 0.f);
            if (row0 + r < NN) val = s4[(size_t)(row0 + r) * 32 + (idx & 31)];
            ((float4*)A)[idx] = val;
        }
    }
    // ---- load W1 (128x128) ----
    {
        const float4* w4 = (const float4*)W1;
        #pragma unroll
        for (int i = 0; i < 16; i++)
            ((float4*)B)[t + 256 * i] = w4[t + 256 * i];
    }
    __syncthreads();

    // ---- phase 1: h = silu(s @ W1 + b1) ----
    float acc[4][4];
    #pragma unroll
    for (int i = 0; i < 4; i++)
        #pragma unroll
        for (int j = 0; j < 4; j++) acc[i][j] = 0.f;

    #pragma unroll 8
    for (int k = 0; k < FD; k++) {
        float4 bv = ((float4*)B)[k * 32 + tx];
        #pragma unroll
        for (int i = 0; i < 4; i++) {
            float a = A[(ty * 4 + i) * FD + k];
            acc[i][0] += a * bv.x; acc[i][1] += a * bv.y;
            acc[i][2] += a * bv.z; acc[i][3] += a * bv.w;
        }
    }
    float4 b1v = ((const float4*)b1)[tx];
    __syncthreads();   // all A reads done before overwrite with h
    #pragma unroll
    for (int i = 0; i < 4; i++) {
        float h0 = acc[i][0] + b1v.x, h1 = acc[i][1] + b1v.y;
        float h2 = acc[i][2] + b1v.z, h3 = acc[i][3] + b1v.w;
        h0 = h0 / (1.f + __expf(-h0));
        h1 = h1 / (1.f + __expf(-h1));
        h2 = h2 / (1.f + __expf(-h2));
        h3 = h3 / (1.f + __expf(-h3));
        ((float4*)A)[(ty * 4 + i) * 32 + tx] = make_float4(h0, h1, h2, h3);
    }
    __syncthreads();

    // ---- phase 2: phi = h @ W2 + b2, 8 column chunks of 128 ----
    for (int g = 0; g < 8; g++) {
        // load W2[:, g*128 : (g+1)*128]  (row stride 1024 floats = 256 f4)
        #pragma unroll
        for (int i = 0; i < 16; i++) {
            int idx = t + 256 * i;
            int r = idx >> 5, c4 = idx & 31;
            ((float4*)B)[idx] = ((const float4*)W2)[(size_t)r * 256 + g * 32 + c4];
        }
        __syncthreads();

        float a2[4][4];
        #pragma unroll
        for (int i = 0; i < 4; i++)
            #pragma unroll
            for (int j = 0; j < 4; j++) a2[i][j] = 0.f;

        #pragma unroll 8
        for (int k = 0; k < FD; k++) {
            float4 bv = ((float4*)B)[k * 32 + tx];
            #pragma unroll
            for (int i = 0; i < 4; i++) {
                float a = A[(ty * 4 + i) * FD + k];
                a2[i][0] += a * bv.x; a2[i][1] += a * bv.y;
                a2[i][2] += a * bv.z; a2[i][3] += a * bv.w;
            }
        }
        float4 b2v = ((const float4*)b2)[g * 32 + tx];
        #pragma unroll
        for (int i = 0; i < 4; i++) {
            int r = row0 + ty * 4 + i;
            if (r < NN) {
                float4 o = make_float4(a2[i][0] + b2v.x, a2[i][1] + b2v.y,
                                       a2[i][2] + b2v.z, a2[i][3] + b2v.w);
                ((float4*)g_phi)[(size_t)r * 256 + g * 32 + tx] = o;
            }
        }
        __syncthreads();
    }
}

// ---------------------------------------------------------------------------
// Fused edge kernel:
//   rc[e] = re1*fc1 + re2*fc2 + re3*fc3                 (folds 3 branches)
//   W[e]  = rc[e] @ Wr + br*(fc1+fc2+fc3)               (K=32 GEMM, smem Wr)
//   x     = phi[idx_j] * W  -> 8 chunks recombined in-register
//   atomicAdd into out_s (+ds), out_v (+dv)
// Block: 512 threads, 16 edges. Thread owns feature f and 4 edges, all 8 chunks.
// ---------------------------------------------------------------------------
#define EB 16
// smem floats: Wr 32*1024  + rc EB*32 + u EB*9 + fs EB ; + 2*EB ints
#define EDGE_SMEM ((32 * 1024 + EB * 32 + EB * 9 + EB) * 4 + EB * 2 * 4)

__global__ __launch_bounds__(512) void edge_kernel(
    const float* __restrict__ re1, const float* __restrict__ re2, const float* __restrict__ re3,
    const float* __restrict__ fc1, const float* __restrict__ fc2, const float* __restrict__ fc3,
    const float* __restrict__ u1, const float* __restrict__ u2, const float* __restrict__ u3,
    const int* __restrict__ eidx,            // int32! (JAX x64 disabled downcasts int64)
    const float* __restrict__ Wr, const float* __restrict__ br,
    const float* __restrict__ v,
    float* __restrict__ out_s, float* __restrict__ out_v)
{
    extern __shared__ float sm[];
    float* wrs = sm;                     // [32][1024]
    float* rc  = sm + 32 * 1024;         // [EB][32]
    float* us  = rc + EB * 32;           // [EB][9]
    float* fss = us + EB * 9;            // [EB]
    int*   ii  = (int*)(fss + EB);       // [EB]
    int*   jj  = ii + EB;                // [EB]

    const int t = threadIdx.x;
    const int e0 = blockIdx.x * EB;

    // ---- stage Wr into smem (32768 floats = 8192 f4 / 512 thr = 16 each) ----
    #pragma unroll
    for (int i = 0; i < 16; i++)
        ((float4*)wrs)[t + 512 * i] = ((const float4*)Wr)[t + 512 * i];

    // ---- per-edge scalars ----
    if (t < EB) {
        int e = e0 + t;
        ii[t] = eidx[e];
        jj[t] = eidx[NE + e];
        fss[t] = fc1[e] + fc2[e] + fc3[e];
    }
    if (t < EB * 9) {
        int e = t / 9, c = t % 9;
        int ge = e0 + e;
        us[t] = (c < 3) ? u1[ge * 3 + c]
              : (c < 6) ? u2[ge * 3 + (c - 3)]
                        : u3[ge * 3 + (c - 6)];
    }
    // ---- rc: EB*32 = 512 values, one per thread ----
    {
        int e = t >> 5, k = t & 31;
        int ge = e0 + e;
        rc[t] = re1[ge * 32 + k] * fc1[ge]
              + re2[ge * 32 + k] * fc2[ge]
              + re3[ge * 32 + k] * fc3[ge];
    }
    __syncthreads();

    const int f  = t & 127;
    const int eb = (t >> 7) * 4;     // first of this thread's 4 edges

    // ---- radial GEMM: acc[e][g] = sum_k rc[e][k] * Wr[k][g*128+f] ----
    float acc[4][8];
    #pragma unroll
    for (int e = 0; e < 4; e++)
        #pragma unroll
        for (int g = 0; g < 8; g++) acc[e][g] = 0.f;

    #pragma unroll 8
    for (int k = 0; k < 32; k++) {
        float wv[8];
        #pragma unroll
        for (int g = 0; g < 8; g++) wv[g] = wrs[k * 1024 + g * 128 + f];  // stride-1: no conflicts
        #pragma unroll
        for (int e = 0; e < 4; e++) {
            float r = rc[(eb + e) * 32 + k];                              // warp-uniform: broadcast
            #pragma unroll
            for (int g = 0; g < 8; g++) acc[e][g] += r * wv[g];
        }
    }

    float brf[8];
    #pragma unroll
    for (int g = 0; g < 8; g++) brf[g] = br[g * 128 + f];

    // ---- epilogue: gather phi_j & v_j, recombine 8 chunks, scatter ----
    #pragma unroll
    for (int e = 0; e < 4; e++) {
        const int le = eb + e;
        const int nj = jj[le];
        const float fsv = fss[le];

        const float* ph = g_phi + (size_t)nj * F8;
        float x[8];
        #pragma unroll
        for (int g = 0; g < 8; g++)
            x[g] = ph[g * 128 + f] * (acc[e][g] + brf[g] * fsv);

        const float* vp = v + (size_t)nj * (3 * FD);
        float vj0 = vp[f], vj1 = vp[FD + f], vj2 = vp[2 * FD + f];

        const float* uu = us + le * 9;
        float u1x = uu[0], u1y = uu[1], u1z = uu[2];
        float u2x = uu[3], u2y = uu[4], u2z = uu[5];
        float u3x = uu[6], u3y = uu[7], u3z = uu[8];

        // x_v = vj*x_vv + sum_k x_vsk*u_k + sum_k x_vck*cross(vj, u_k)
        float dv0 = vj0 * x[1] + x[2] * u1x + x[3] * u2x + x[4] * u3x
                  + x[5] * (vj1 * u1z - vj2 * u1y)
                  + x[6] * (vj1 * u2z - vj2 * u2y)
                  + x[7] * (vj1 * u3z - vj2 * u3y);
        float dv1 = vj1 * x[1] + x[2] * u1y + x[3] * u2y + x[4] * u3y
                  + x[5] * (vj2 * u1x - vj0 * u1z)
                  + x[6] * (vj2 * u2x - vj0 * u2z)
                  + x[7] * (vj2 * u3x - vj0 * u3z);
        float dv2 = vj2 * x[1] + x[2] * u1z + x[3] * u2z + x[4] * u3z
                  + x[5] * (vj0 * u1y - vj1 * u1x)
                  + x[6] * (vj0 * u2y - vj1 * u2x)
                  + x[7] * (vj0 * u3y - vj1 * u3x);

        const int ni = ii[le];
        atomicAdd(out_s + (size_t)ni * FD + f, x[0]);
        float* ov = out_v + (size_t)ni * (3 * FD) + f;
        atomicAdd(ov,          dv0);
        atomicAdd(ov + FD,     dv1);
        atomicAdd(ov + 2 * FD, dv2);
    }
}

// ---------------------------------------------------------------------------
extern "C" void kernel_launch(void* const* d_in, const int* in_sizes, int n_in,
                              void* d_out, int out_size)
{
    const float* s    = (const float*)d_in[0];
    const float* v    = (const float*)d_in[1];
    const float* re1  = (const float*)d_in[2];
    const float* re2  = (const float*)d_in[3];
    const float* re3  = (const float*)d_in[4];
    const float* fc1  = (const float*)d_in[5];
    const float* fc2  = (const float*)d_in[6];
    const float* fc3  = (const float*)d_in[7];
    const float* u1   = (const float*)d_in[8];
    const float* u2   = (const float*)d_in[9];
    const float* u3   = (const float*)d_in[10];
    const int*   eidx = (const int*)d_in[11];     // int32 (JAX default x64-off)
    const float* W1   = (const float*)d_in[12];
    const float* b1   = (const float*)d_in[13];
    const float* W2   = (const float*)d_in[14];
    const float* b2   = (const float*)d_in[15];
    const float* Wr   = (const float*)d_in[16];
    const float* br   = (const float*)d_in[17];

    float* out_s = (float*)d_out;
    float* out_v = out_s + (size_t)NN * FD;

    cudaFuncSetAttribute(phi_kernel,  cudaFuncAttributeMaxDynamicSharedMemorySize, PHI_SMEM);
    cudaFuncSetAttribute(edge_kernel, cudaFuncAttributeMaxDynamicSharedMemorySize, EDGE_SMEM);

    // out = (s, v) baseline; edge kernel accumulates ds/dv on top
    cudaMemcpyAsync(out_s, s, (size_t)NN * FD * sizeof(float),     cudaMemcpyDeviceToDevice, 0);
    cudaMemcpyAsync(out_v, v, (size_t)NN * 3 * FD * sizeof(float), cudaMemcpyDeviceToDevice, 0);

    phi_kernel<<<(NN + PHI_BM - 1) / PHI_BM, 256, PHI_SMEM>>>(s, W1, b1, W2, b2);

    edge_kernel<<<NE / EB, 512, EDGE_SMEM>>>(re1, re2, re3, fc1, fc2, fc3,
                                             u1, u2, u3, eidx, Wr, br, v,
                                             out_s, out_v);
}

// round 12
// speedup vs baseline: 1.2803x; 1.2803x over previous
#include <cuda_runtime.h>
#include <cuda_bf16.h>
#include <cstdint>

#define NN 10000
#define NE 160000
#define FD 128
#define F8 1024

__device__ float g_phi[(size_t)NN * F8];

// ===========================================================================
// warp-level bf16 MMA (sm_80+ baseline feature — portable to compute_103)
// D[16f x 8e] += A[16f x 16k] * B[16k x 8e],  fp32 accumulate
// ===========================================================================
__device__ __forceinline__ void mma_bf16(float d[4],
    uint32_t a0, uint32_t a1, uint32_t a2, uint32_t a3,
    uint32_t b0, uint32_t b1)
{
    asm volatile(
        "mma.sync.aligned.m16n8k16.row.col.f32.bf16.bf16.f32 "
        "{%0,%1,%2,%3}, {%4,%5,%6,%7}, {%8,%9}, {%0,%1,%2,%3};\n"
        : "+f"(d[0]), "+f"(d[1]), "+f"(d[2]), "+f"(d[3])
        : "r"(a0), "r"(a1), "r"(a2), "r"(a3), "r"(b0), "r"(b1));
}

// ===========================================================================
// phi = silu(s @ W1 + b1) @ W2 + b2   (unchanged from R6 — fp32 smem-tiled)
// ===========================================================================
#define PHI_BM 32
#define PHI_SMEM ((PHI_BM * FD + FD * FD) * 4)

__global__ __launch_bounds__(256) void phi_kernel(
    const float* __restrict__ s,
    const float* __restrict__ W1, const float* __restrict__ b1,
    const float* __restrict__ W2, const float* __restrict__ b2)
{
    extern __shared__ float sm[];
    float* A = sm;
    float* B = sm + PHI_BM * FD;

    const int t = threadIdx.x;
    const int row0 = blockIdx.x * PHI_BM;
    const int tx = t & 31;
    const int ty = t >> 5;

    {
        const float4* s4 = (const float4*)s;
        #pragma unroll
        for (int i = 0; i < 4; i++) {
            int idx = t + 256 * i;
            int r = idx >> 5;
            float4 val = make_float4(0.f, 0.f, 0.f, 0.f);
            if (row0 + r < NN) val = s4[(size_t)(row0 + r) * 32 + (idx & 31)];
            ((float4*)A)[idx] = val;
        }
    }
    {
        const float4* w4 = (const float4*)W1;
        #pragma unroll
        for (int i = 0; i < 16; i++)
            ((float4*)B)[t + 256 * i] = w4[t + 256 * i];
    }
    __syncthreads();

    float acc[4][4];
    #pragma unroll
    for (int i = 0; i < 4; i++)
        #pragma unroll
        for (int j = 0; j < 4; j++) acc[i][j] = 0.f;

    #pragma unroll 8
    for (int k = 0; k < FD; k++) {
        float4 bv = ((float4*)B)[k * 32 + tx];
        #pragma unroll
        for (int i = 0; i < 4; i++) {
            float a = A[(ty * 4 + i) * FD + k];
            acc[i][0] += a * bv.x; acc[i][1] += a * bv.y;
            acc[i][2] += a * bv.z; acc[i][3] += a * bv.w;
        }
    }
    float4 b1v = ((const float4*)b1)[tx];
    __syncthreads();
    #pragma unroll
    for (int i = 0; i < 4; i++) {
        float h0 = acc[i][0] + b1v.x, h1 = acc[i][1] + b1v.y;
        float h2 = acc[i][2] + b1v.z, h3 = acc[i][3] + b1v.w;
        h0 = h0 / (1.f + __expf(-h0));
        h1 = h1 / (1.f + __expf(-h1));
        h2 = h2 / (1.f + __expf(-h2));
        h3 = h3 / (1.f + __expf(-h3));
        ((float4*)A)[(ty * 4 + i) * 32 + tx] = make_float4(h0, h1, h2, h3);
    }
    __syncthreads();

    for (int g = 0; g < 8; g++) {
        #pragma unroll
        for (int i = 0; i < 16; i++) {
            int idx = t + 256 * i;
            int r = idx >> 5, c4 = idx & 31;
            ((float4*)B)[idx] = ((const float4*)W2)[(size_t)r * 256 + g * 32 + c4];
        }
        __syncthreads();

        float a2[4][4];
        #pragma unroll
        for (int i = 0; i < 4; i++)
            #pragma unroll
            for (int j = 0; j < 4; j++) a2[i][j] = 0.f;

        #pragma unroll 8
        for (int k = 0; k < FD; k++) {
            float4 bv = ((float4*)B)[k * 32 + tx];
            #pragma unroll
            for (int i = 0; i < 4; i++) {
                float a = A[(ty * 4 + i) * FD + k];
                a2[i][0] += a * bv.x; a2[i][1] += a * bv.y;
                a2[i][2] += a * bv.z; a2[i][3] += a * bv.w;
            }
        }
        float4 b2v = ((const float4*)b2)[g * 32 + tx];
        #pragma unroll
        for (int i = 0; i < 4; i++) {
            int r = row0 + ty * 4 + i;
            if (r < NN) {
                float4 o = make_float4(a2[i][0] + b2v.x, a2[i][1] + b2v.y,
                                       a2[i][2] + b2v.z, a2[i][3] + b2v.w);
                ((float4*)g_phi)[(size_t)r * 256 + g * 32 + tx] = o;
            }
        }
        __syncthreads();
    }
}

// ===========================================================================
// Edge kernel — mma.sync bf16 3-pass radial GEMM + fused epilogue
//
// Per 16-edge tile:  C[f, e] = sum_k WrT[f, k] * rc[e, k]   (f over 1024)
//   As smem: [1024 f][row 144B: 32 bf16 hi | 32 bf16 lo | 8 pad]  staged once
//   rcs smem: [16 e][row 144B: hi | lo | pad]                     per tile
// Warp w: f-tile (w&7)*16 within each chunk, e-subtile (w>>3)*8.
// 3 passes (hiA*hiB, hiA*loB, loA*hiB) x 2 k-steps x 8 chunks = 48 mma/warp.
// Accumulators acc[8][4] live in registers; epilogue combines the warp's own
// (f,e) positions (thread: f in {grp, grp+8}, e in {qid*2, qid*2+1}).
// ===========================================================================
#define ET 16
#define NT (NE / ET)    // 10000
#define EGRID 152

// smem byte offsets
#define SM_AS   0                        // 1024 * 144 = 147456
#define SM_RC   147456                   // 16 * 144   = 2304
#define SM_BR   149760                   // 1024 * 4   = 4096
#define SM_US   153856                   // 16*9*4     = 576
#define SM_FSS  154432                   // 64
#define SM_II   154496                   // 64
#define SM_JJ   154560                   // 64
#define EDGE_SMEM 154624

__global__ __launch_bounds__(512, 1) void edge_kernel(
    const float* __restrict__ re1, const float* __restrict__ re2, const float* __restrict__ re3,
    const float* __restrict__ fc1, const float* __restrict__ fc2, const float* __restrict__ fc3,
    const float* __restrict__ u1, const float* __restrict__ u2, const float* __restrict__ u3,
    const int* __restrict__ eidx,
    const float* __restrict__ Wr, const float* __restrict__ br,
    const float* __restrict__ v,
    float* __restrict__ out_s, float* __restrict__ out_v)
{
    extern __shared__ char smc[];
    const int t    = threadIdx.x;
    const int lane = t & 31;
    const int wid  = t >> 5;
    const int grp  = lane >> 2;      // 0..7  (fragment row group)
    const int qid  = lane & 3;       // 0..3  (fragment col group)
    const int ftile = (wid & 7) * 16;     // f offset within a 128-chunk
    const int esub  = (wid >> 3) * 8;     // 0 or 8

    float* brs = (float*)(smc + SM_BR);
    float* us  = (float*)(smc + SM_US);
    float* fss = (float*)(smc + SM_FSS);
    int*   ii  = (int*)(smc + SM_II);
    int*   jj  = (int*)(smc + SM_JJ);

    // ---- stage WrT hi/lo into As, once per block (coalesced over f) ----
    #pragma unroll 4
    for (int i = 0; i < 64; i++) {
        int idx = t + 512 * i;           // 0..32767
        int k   = idx >> 10;             // 0..31
        int row = idx & 1023;            // f 0..1023
        float val = Wr[k * 1024 + row];
        __nv_bfloat16 hi = __float2bfloat16_rn(val);
        __nv_bfloat16 lo = __float2bfloat16_rn(val - __bfloat162float(hi));
        char* rp = smc + SM_AS + row * 144;
        *(__nv_bfloat16*)(rp + 2 * k)      = hi;
        *(__nv_bfloat16*)(rp + 64 + 2 * k) = lo;
    }
    for (int i = t; i < 1024; i += 512) brs[i] = br[i];
    // visibility covered by the first in-loop __syncthreads()

    for (int tile = blockIdx.x; tile < NT; tile += EGRID) {
        const int e0 = tile * ET;

        // ---- stage rc tile hi/lo: thread -> (e = t>>5, k = t&31) ----
        {
            int e = t >> 5, k = t & 31;
            int ge = e0 + e;
            float val = re1[ge * 32 + k] * fc1[ge]
                      + re2[ge * 32 + k] * fc2[ge]
                      + re3[ge * 32 + k] * fc3[ge];
            __nv_bfloat16 hi = __float2bfloat16_rn(val);
            __nv_bfloat16 lo = __float2bfloat16_rn(val - __bfloat162float(hi));
            char* rp = smc + SM_RC + e * 144;
            *(__nv_bfloat16*)(rp + 2 * k)      = hi;
            *(__nv_bfloat16*)(rp + 64 + 2 * k) = lo;
        }
        if (t < ET) {
            int ge = e0 + t;
            ii[t]  = eidx[ge];
            jj[t]  = eidx[NE + ge];
            fss[t] = fc1[ge] + fc2[ge] + fc3[ge];
        }
        if (t < ET * 9) {
            int e = t / 9, c = t % 9;
            int ge = e0 + e;
            us[t] = (c < 3) ? u1[ge * 3 + c]
                  : (c < 6) ? u2[ge * 3 + (c - 3)]
                            : u3[ge * 3 + (c - 6)];
        }
        __syncthreads();

        // ---- B fragments (rc), loaded once, reused across all 8 chunks ----
        const char* brow = smc + SM_RC + (esub + grp) * 144 + qid * 4;
        const uint32_t bh00 = *(const uint32_t*)(brow);        // hi ks0: k=qid*2,+1
        const uint32_t bh01 = *(const uint32_t*)(brow + 16);   //         k+8,+9
        const uint32_t bh10 = *(const uint32_t*)(brow + 32);   // hi ks1
        const uint32_t bh11 = *(const uint32_t*)(brow + 48);
        const uint32_t bl00 = *(const uint32_t*)(brow + 64);   // lo ks0
        const uint32_t bl01 = *(const uint32_t*)(brow + 80);
        const uint32_t bl10 = *(const uint32_t*)(brow + 96);   // lo ks1
        const uint32_t bl11 = *(const uint32_t*)(brow + 112);

        float acc[8][4];
        #pragma unroll
        for (int g = 0; g < 8; g++) {
            acc[g][0] = 0.f; acc[g][1] = 0.f; acc[g][2] = 0.f; acc[g][3] = 0.f;
        }

        // ---- 48 mma: 8 chunks x (3 passes x 2 k-steps) ----
        #pragma unroll
        for (int g = 0; g < 8; g++) {
            const char* ar0 = smc + SM_AS + (g * 128 + ftile + grp) * 144 + qid * 4;
            const char* ar1 = ar0 + 8 * 144;
            uint32_t a0, a1, a2, a3;
            // hiA, ks0
            a0 = *(const uint32_t*)(ar0);      a1 = *(const uint32_t*)(ar1);
            a2 = *(const uint32_t*)(ar0 + 16); a3 = *(const uint32_t*)(ar1 + 16);
            mma_bf16(acc[g], a0, a1, a2, a3, bh00, bh01);   // hi*hi
            mma_bf16(acc[g], a0, a1, a2, a3, bl00, bl01);   // hi*lo
            // hiA, ks1
            a0 = *(const uint32_t*)(ar0 + 32); a1 = *(const uint32_t*)(ar1 + 32);
            a2 = *(const uint32_t*)(ar0 + 48); a3 = *(const uint32_t*)(ar1 + 48);
            mma_bf16(acc[g], a0, a1, a2, a3, bh10, bh11);
            mma_bf16(acc[g], a0, a1, a2, a3, bl10, bl11);
            // loA, ks0 (lo*hi)
            a0 = *(const uint32_t*)(ar0 + 64); a1 = *(const uint32_t*)(ar1 + 64);
            a2 = *(const uint32_t*)(ar0 + 80); a3 = *(const uint32_t*)(ar1 + 80);
            mma_bf16(acc[g], a0, a1, a2, a3, bh00, bh01);
            // loA, ks1
            a0 = *(const uint32_t*)(ar0 + 96);  a1 = *(const uint32_t*)(ar1 + 96);
            a2 = *(const uint32_t*)(ar0 + 112); a3 = *(const uint32_t*)(ar1 + 112);
            mma_bf16(acc[g], a0, a1, a2, a3, bh10, bh11);
        }

        // ---- epilogue: thread owns (f in {grp, grp+8}) x (e in {qid*2,+1}) ----
        #pragma unroll
        for (int pf = 0; pf < 2; pf++) {
            const int fl = ftile + grp + pf * 8;      // feature within chunk
            float brf[8];
            #pragma unroll
            for (int g = 0; g < 8; g++) brf[g] = brs[g * 128 + fl];

            #pragma unroll
            for (int pe = 0; pe < 2; pe++) {
                const int le  = esub + qid * 2 + pe;
                const int pos = pf * 2 + pe;
                const int nj  = jj[le];
                const float fsv = fss[le];

                const float* ph = g_phi + (size_t)nj * F8 + fl;
                float x[8];
                #pragma unroll
                for (int g = 0; g < 8; g++)
                    x[g] = ph[g * 128] * (acc[g][pos] + brf[g] * fsv);

                const float* vp = v + (size_t)nj * (3 * FD) + fl;
                float vj0 = vp[0], vj1 = vp[FD], vj2 = vp[2 * FD];

                const float* uu = us + le * 9;
                float u1x = uu[0], u1y = uu[1], u1z = uu[2];
                float u2x = uu[3], u2y = uu[4], u2z = uu[5];
                float u3x = uu[6], u3y = uu[7], u3z = uu[8];

                float dv0 = vj0 * x[1] + x[2] * u1x + x[3] * u2x + x[4] * u3x
                          + x[5] * (vj1 * u1z - vj2 * u1y)
                          + x[6] * (vj1 * u2z - vj2 * u2y)
                          + x[7] * (vj1 * u3z - vj2 * u3y);
                float dv1 = vj1 * x[1] + x[2] * u1y + x[3] * u2y + x[4] * u3y
                          + x[5] * (vj2 * u1x - vj0 * u1z)
                          + x[6] * (vj2 * u2x - vj0 * u2z)
                          + x[7] * (vj2 * u3x - vj0 * u3z);
                float dv2 = vj2 * x[1] + x[2] * u1z + x[3] * u2z + x[4] * u3z
                          + x[5] * (vj0 * u1y - vj1 * u1x)
                          + x[6] * (vj0 * u2y - vj1 * u2x)
                          + x[7] * (vj0 * u3y - vj1 * u3x);

                const int ni = ii[le];
                atomicAdd(out_s + (size_t)ni * FD + fl, x[0]);
                float* ov = out_v + (size_t)ni * (3 * FD) + fl;
                atomicAdd(ov,          dv0);
                atomicAdd(ov + FD,     dv1);
                atomicAdd(ov + 2 * FD, dv2);
            }
        }
        __syncthreads();   // epilogue smem reads done before next tile restages
    }
}

// ===========================================================================
extern "C" void kernel_launch(void* const* d_in, const int* in_sizes, int n_in,
                              void* d_out, int out_size)
{
    const float* s    = (const float*)d_in[0];
    const float* v    = (const float*)d_in[1];
    const float* re1  = (const float*)d_in[2];
    const float* re2  = (const float*)d_in[3];
    const float* re3  = (const float*)d_in[4];
    const float* fc1  = (const float*)d_in[5];
    const float* fc2  = (const float*)d_in[6];
    const float* fc3  = (const float*)d_in[7];
    const float* u1   = (const float*)d_in[8];
    const float* u2   = (const float*)d_in[9];
    const float* u3   = (const float*)d_in[10];
    const int*   eidx = (const int*)d_in[11];
    const float* W1   = (const float*)d_in[12];
    const float* b1   = (const float*)d_in[13];
    const float* W2   = (const float*)d_in[14];
    const float* b2   = (const float*)d_in[15];
    const float* Wr   = (const float*)d_in[16];
    const float* br   = (const float*)d_in[17];

    float* out_s = (float*)d_out;
    float* out_v = out_s + (size_t)NN * FD;

    cudaFuncSetAttribute(phi_kernel,  cudaFuncAttributeMaxDynamicSharedMemorySize, PHI_SMEM);
    cudaFuncSetAttribute(edge_kernel, cudaFuncAttributeMaxDynamicSharedMemorySize, EDGE_SMEM);

    cudaMemcpyAsync(out_s, s, (size_t)NN * FD * sizeof(float),     cudaMemcpyDeviceToDevice, 0);
    cudaMemcpyAsync(out_v, v, (size_t)NN * 3 * FD * sizeof(float), cudaMemcpyDeviceToDevice, 0);

    phi_kernel<<<(NN + PHI_BM - 1) / PHI_BM, 256, PHI_SMEM>>>(s, W1, b1, W2, b2);

    edge_kernel<<<EGRID, 512, EDGE_SMEM>>>(re1, re2, re3, fc1, fc2, fc3,
                                           u1, u2, u3, eidx, Wr, br, v,
                                           out_s, out_v);
}

// round 14
// speedup vs baseline: 1.5537x; 1.2136x over previous
#include <cuda_runtime.h>
#include <cuda_bf16.h>
#include <cstdint>

#define NN 10000
#define NE 160000
#define FD 128
#define F8 1024

__device__ float g_phi[(size_t)NN * F8];

// ===========================================================================
// warp-level bf16 MMA (sm_80+ baseline — portable to compute_103)
// D[16 x 8] += A[16 x 16k] * B[16k x 8],  fp32 accumulate
// ===========================================================================
__device__ __forceinline__ void mma_bf16(float d[4],
    uint32_t a0, uint32_t a1, uint32_t a2, uint32_t a3,
    uint32_t b0, uint32_t b1)
{
    asm volatile(
        "mma.sync.aligned.m16n8k16.row.col.f32.bf16.bf16.f32 "
        "{%0,%1,%2,%3}, {%4,%5,%6,%7}, {%8,%9}, {%0,%1,%2,%3};\n"
        : "+f"(d[0]), "+f"(d[1]), "+f"(d[2]), "+f"(d[3])
        : "r"(a0), "r"(a1), "r"(a2), "r"(a3), "r"(b0), "r"(b1));
}

__device__ __forceinline__ uint32_t pack_bf16x2(float lo_val, float hi_val) {
    __nv_bfloat162 p = __floats2bfloat162_rn(lo_val, hi_val);
    return *(uint32_t*)&p;
}

// ===========================================================================
// phi = silu(s @ W1 + b1) @ W2 + b2
// Phase 1 (s@W1+silu): fp32 smem-tiled (10% of flops).
// Phase 2 (h@W2):      bf16 hi/lo 3-pass mma.sync (90% of flops).
// Block: 256 threads (8 warps), BM=32 node rows.
// smem: phase1 As[32][128]f32 @0 (16KB), Bs=W1 @16384 (64KB)
//       then  hA rows 528B @0 (16896), W2T rows 528B @17408 (67584),
//       b2s @84992 (4096) -> total 89088
// ===========================================================================
#define PHI_BM 32
#define PHI_HA    0
#define PHI_W2T   17408
#define PHI_B2S   84992
#define PHI_SMEM  89088

__global__ __launch_bounds__(256) void phi_kernel(
    const float* __restrict__ s,
    const float* __restrict__ W1, const float* __restrict__ b1,
    const float* __restrict__ W2, const float* __restrict__ b2)
{
    extern __shared__ char smc[];
    float* A = (float*)smc;                  // phase1: s tile [32][128]
    float* B = (float*)(smc + 16384);        // phase1: W1 [128][128]
    float* b2s = (float*)(smc + PHI_B2S);

    const int t = threadIdx.x;
    const int row0 = blockIdx.x * PHI_BM;
    const int tx = t & 31;
    const int ty = t >> 5;
    const int lane = t & 31;
    const int wid  = t >> 5;
    const int grp  = lane >> 2;
    const int qid  = lane & 3;

    // ---- stage b2 (independent region) ----
    for (int i = t; i < 1024; i += 256) b2s[i] = b2[i];

    // ---- phase 1 staging ----
    {
        const float4* s4 = (const float4*)s;
        #pragma unroll
        for (int i = 0; i < 4; i++) {
            int idx = t + 256 * i;
            int r = idx >> 5;
            float4 val = make_float4(0.f, 0.f, 0.f, 0.f);
            if (row0 + r < NN) val = s4[(size_t)(row0 + r) * 32 + (idx & 31)];
            ((float4*)A)[idx] = val;
        }
        const float4* w4 = (const float4*)W1;
        #pragma unroll
        for (int i = 0; i < 16; i++)
            ((float4*)B)[t + 256 * i] = w4[t + 256 * i];
    }
    __syncthreads();

    // ---- phase 1: h = silu(s @ W1 + b1) ----
    float acc1[4][4];
    #pragma unroll
    for (int i = 0; i < 4; i++)
        #pragma unroll
        for (int j = 0; j < 4; j++) acc1[i][j] = 0.f;

    #pragma unroll 8
    for (int k = 0; k < FD; k++) {
        float4 bv = ((float4*)B)[k * 32 + tx];
        #pragma unroll
        for (int i = 0; i < 4; i++) {
            float a = A[(ty * 4 + i) * FD + k];
            acc1[i][0] += a * bv.x; acc1[i][1] += a * bv.y;
            acc1[i][2] += a * bv.z; acc1[i][3] += a * bv.w;
        }
    }
    float4 b1v = ((const float4*)b1)[tx];
    __syncthreads();   // As/Bs reads done before hA overwrite

    // ---- write h as bf16 hi/lo into hA rows (528B stride) ----
    #pragma unroll
    for (int i = 0; i < 4; i++) {
        float h[4];
        h[0] = acc1[i][0] + b1v.x; h[1] = acc1[i][1] + b1v.y;
        h[2] = acc1[i][2] + b1v.z; h[3] = acc1[i][3] + b1v.w;
        #pragma unroll
        for (int j = 0; j < 4; j++) h[j] = h[j] / (1.f + __expf(-h[j]));

        __nv_bfloat16 hh[4];
        float         hl[4];
        #pragma unroll
        for (int j = 0; j < 4; j++) {
            hh[j] = __float2bfloat16_rn(h[j]);
            hl[j] = h[j] - __bfloat162float(hh[j]);
        }
        char* rp = smc + PHI_HA + (ty * 4 + i) * 528;
        uint2 hiw, low;
        { __nv_bfloat162 p0 = {hh[0], hh[1]}, p1 = {hh[2], hh[3]};
          hiw.x = *(uint32_t*)&p0; hiw.y = *(uint32_t*)&p1; }
        low.x = pack_bf16x2(hl[0], hl[1]);
        low.y = pack_bf16x2(hl[2], hl[3]);
        *(uint2*)(rp + 8 * tx)       = hiw;
        *(uint2*)(rp + 256 + 8 * tx) = low;
    }
    __syncthreads();

    // ---- phase 2: phi = h @ W2 + b2  (mma, per 128-col chunk g) ----
    const int mtile = wid & 1;            // 0,1 -> rows 0-15 / 16-31
    const int nbase = (wid >> 1) * 32;    // 0,32,64,96

    for (int g = 0; g < 8; g++) {
        // stage W2T chunk: rows n (128) x [hi 256B | lo 256B], 528B stride
        #pragma unroll 4
        for (int q = 0; q < 32; q++) {
            int k = 4 * q + 2 * (t >> 7);      // even
            int n = t & 127;
            float v0 = W2[(size_t)k * 1024 + g * 128 + n];
            float v1 = W2[(size_t)(k + 1) * 1024 + g * 128 + n];
            __nv_bfloat16 h0 = __float2bfloat16_rn(v0);
            __nv_bfloat16 h1 = __float2bfloat16_rn(v1);
            float l0 = v0 - __bfloat162float(h0);
            float l1 = v1 - __bfloat162float(h1);
            char* rp = smc + PHI_W2T + n * 528;
            __nv_bfloat162 hp = {h0, h1};
            *(uint32_t*)(rp + 2 * k)       = *(uint32_t*)&hp;
            *(uint32_t*)(rp + 256 + 2 * k) = pack_bf16x2(l0, l1);
        }
        __syncthreads();

        float acc[4][4];
        #pragma unroll
        for (int nt = 0; nt < 4; nt++) {
            acc[nt][0] = 0.f; acc[nt][1] = 0.f; acc[nt][2] = 0.f; acc[nt][3] = 0.f;
        }

        #pragma unroll
        for (int ks = 0; ks < 8; ks++) {
            const char* ar  = smc + PHI_HA + (mtile * 16 + grp) * 528 + ks * 32 + qid * 4;
            const char* ar8 = ar + 8 * 528;
            uint32_t ah0 = *(const uint32_t*)(ar);
            uint32_t ah1 = *(const uint32_t*)(ar8);
            uint32_t ah2 = *(const uint32_t*)(ar + 16);
            uint32_t ah3 = *(const uint32_t*)(ar8 + 16);
            uint32_t al0 = *(const uint32_t*)(ar + 256);
            uint32_t al1 = *(const uint32_t*)(ar8 + 256);
            uint32_t al2 = *(const uint32_t*)(ar + 272);
            uint32_t al3 = *(const uint32_t*)(ar8 + 272);
            #pragma unroll
            for (int nt = 0; nt < 4; nt++) {
                const char* brp = smc + PHI_W2T + (nbase + nt * 8 + grp) * 528 + ks * 32 + qid * 4;
                uint32_t bh0 = *(const uint32_t*)(brp);
                uint32_t bh1 = *(const uint32_t*)(brp + 16);
                uint32_t bl0 = *(const uint32_t*)(brp + 256);
                uint32_t bl1 = *(const uint32_t*)(brp + 272);
                mma_bf16(acc[nt], ah0, ah1, ah2, ah3, bh0, bh1);   // hi*hi
                mma_bf16(acc[nt], ah0, ah1, ah2, ah3, bl0, bl1);   // hi*lo
                mma_bf16(acc[nt], al0, al1, al2, al3, bh0, bh1);   // lo*hi
            }
        }
        __syncthreads();   // frag reads done before next g restages W2T

        // epilogue: write phi chunk
        #pragma unroll
        for (int nt = 0; nt < 4; nt++) {
            int n = nbase + nt * 8 + qid * 2;
            float bb0 = b2s[g * 128 + n], bb1 = b2s[g * 128 + n + 1];
            int r = row0 + mtile * 16 + grp;
            if (r < NN) {
                float2 o = make_float2(acc[nt][0] + bb0, acc[nt][1] + bb1);
                *(float2*)&g_phi[(size_t)r * 1024 + g * 128 + n] = o;
            }
            int r2 = r + 8;
            if (r2 < NN) {
                float2 o = make_float2(acc[nt][2] + bb0, acc[nt][3] + bb1);
                *(float2*)&g_phi[(size_t)r2 * 1024 + g * 128 + n] = o;
            }
        }
    }
}

// ===========================================================================
// Edge kernel — mma.sync bf16 3-pass radial GEMM + fused epilogue
// ET=32 edges/tile, double-buffered staging, ONE __syncthreads per tile.
// Warp w: f-tile (w&7)*16, e-half (w>>3)*16 -> two 8-edge subtiles.
// ===========================================================================
#define ET 32
#define NT (NE / ET)    // 5000
#define EGRID 152

// smem byte offsets
#define SM_AS   0                        // 1024 * 144 = 147456
#define SM_BRS  147456                   // 4096
#define SM_T0   151552                   // tile buffer 0 (6144B)
#define SM_T1   157696                   // tile buffer 1 (6144B)
// within a tile buffer: rc 0..4607 (32 rows x 144B), us 4608..5759,
//                       fss 5760..5887, ii 5888..6015, jj 6016..6143
#define TB_US   4608
#define TB_FSS  5760
#define TB_II   5888
#define TB_JJ   6016
#define EDGE_SMEM 163840

__global__ __launch_bounds__(512, 1) void edge_kernel(
    const float* __restrict__ re1, const float* __restrict__ re2, const float* __restrict__ re3,
    const float* __restrict__ fc1, const float* __restrict__ fc2, const float* __restrict__ fc3,
    const float* __restrict__ u1, const float* __restrict__ u2, const float* __restrict__ u3,
    const int* __restrict__ eidx,
    const float* __restrict__ Wr, const float* __restrict__ br,
    const float* __restrict__ v,
    float* __restrict__ out_s, float* __restrict__ out_v)
{
    extern __shared__ char smc[];
    const int t    = threadIdx.x;
    const int lane = t & 31;
    const int wid  = t >> 5;
    const int grp  = lane >> 2;
    const int qid  = lane & 3;
    const int ftile = (wid & 7) * 16;
    const int ehalf = (wid >> 3);          // 0 or 1

    float* brs = (float*)(smc + SM_BRS);

    // ---- stage WrT hi/lo into As, once per block ----
    #pragma unroll 4
    for (int i = 0; i < 64; i++) {
        int idx = t + 512 * i;           // 0..32767
        int k   = idx >> 10;
        int row = idx & 1023;
        float val = Wr[k * 1024 + row];
        __nv_bfloat16 hi = __float2bfloat16_rn(val);
        float lo = val - __bfloat162float(hi);
        char* rp = smc + SM_AS + row * 144;
        *(__nv_bfloat16*)(rp + 2 * k)      = hi;
        *(__nv_bfloat16*)(rp + 64 + 2 * k) = __float2bfloat16_rn(lo);
    }
    for (int i = t; i < 1024; i += 512) brs[i] = br[i];

    // ---- prologue: stage first tile into buf0 ----
    {
        char* bnx = smc + SM_T0;
        int e0n = blockIdx.x * ET;
        {
            int e = t >> 4, k2 = (t & 15) * 2;
            int ge = e0n + e;
            float f1 = fc1[ge], f2 = fc2[ge], f3 = fc3[ge];
            float v0 = re1[ge * 32 + k2] * f1 + re2[ge * 32 + k2] * f2 + re3[ge * 32 + k2] * f3;
            float v1 = re1[ge * 32 + k2 + 1] * f1 + re2[ge * 32 + k2 + 1] * f2 + re3[ge * 32 + k2 + 1] * f3;
            __nv_bfloat16 h0 = __float2bfloat16_rn(v0), h1 = __float2bfloat16_rn(v1);
            float l0 = v0 - __bfloat162float(h0), l1 = v1 - __bfloat162float(h1);
            char* rp = bnx + e * 144;
            __nv_bfloat162 hp = {h0, h1};
            *(uint32_t*)(rp + 4 * (t & 15))      = *(uint32_t*)&hp;
            *(uint32_t*)(rp + 64 + 4 * (t & 15)) = pack_bf16x2(l0, l1);
        }
        if (t < ET * 9) {
            int e = t / 9, c = t % 9;
            int ge = e0n + e;
            ((float*)(bnx + TB_US))[t] =
                  (c < 3) ? u1[ge * 3 + c]
                : (c < 6) ? u2[ge * 3 + (c - 3)]
                          : u3[ge * 3 + (c - 6)];
        }
        if (t < ET) {
            int ge = e0n + t;
            ((float*)(bnx + TB_FSS))[t] = fc1[ge] + fc2[ge] + fc3[ge];
            ((int*)(bnx + TB_II))[t] = eidx[ge];
            ((int*)(bnx + TB_JJ))[t] = eidx[NE + ge];
        }
    }
    __syncthreads();

    int iter = 0;
    for (int tile = blockIdx.x; tile < NT; tile += EGRID, iter++) {
        char* buf = smc + ((iter & 1) ? SM_T1 : SM_T0);
        char* bnx = smc + ((iter & 1) ? SM_T0 : SM_T1);
        const int tnext = tile + EGRID;
        const bool do_next = tnext < NT;

        // ---- A) issue prefetch LDGs for next tile (values land during compute)
        float p_f0 = 0.f, p_f1 = 0.f, p_f2 = 0.f;
        float p_r0 = 0.f, p_r1 = 0.f, p_r2 = 0.f, p_r3 = 0.f, p_r4 = 0.f, p_r5 = 0.f;
        float p_u = 0.f, p_g1 = 0.f, p_g2 = 0.f, p_g3 = 0.f;
        int   p_ii = 0, p_jj = 0;
        if (do_next) {
            int e0n = tnext * ET;
            {
                int e = t >> 4, k2 = (t & 15) * 2;
                int ge = e0n + e;
                p_f0 = fc1[ge]; p_f1 = fc2[ge]; p_f2 = fc3[ge];
                p_r0 = re1[ge * 32 + k2];     p_r1 = re2[ge * 32 + k2];     p_r2 = re3[ge * 32 + k2];
                p_r3 = re1[ge * 32 + k2 + 1]; p_r4 = re2[ge * 32 + k2 + 1]; p_r5 = re3[ge * 32 + k2 + 1];
            }
            if (t < ET * 9) {
                int e = t / 9, c = t % 9;
                int ge = e0n + e;
                p_u = (c < 3) ? u1[ge * 3 + c]
                    : (c < 6) ? u2[ge * 3 + (c - 3)]
                              : u3[ge * 3 + (c - 6)];
            }
            if (t < ET) {
                int ge = e0n + t;
                p_g1 = fc1[ge]; p_g2 = fc2[ge]; p_g3 = fc3[ge];
                p_ii = eidx[ge]; p_jj = eidx[NE + ge];
            }
        }

        // ---- B) compute current tile: 2 e-subtiles per warp ----
        float* us  = (float*)(buf + TB_US);
        float* fss = (float*)(buf + TB_FSS);
        int*   ii  = (int*)(buf + TB_II);
        int*   jj  = (int*)(buf + TB_JJ);

        #pragma unroll
        for (int sub = 0; sub < 2; sub++) {
            const int esub = ehalf * 16 + sub * 8;

            const char* brow = buf + (esub + grp) * 144 + qid * 4;
            const uint32_t bh00 = *(const uint32_t*)(brow);
            const uint32_t bh01 = *(const uint32_t*)(brow + 16);
            const uint32_t bh10 = *(const uint32_t*)(brow + 32);
            const uint32_t bh11 = *(const uint32_t*)(brow + 48);
            const uint32_t bl00 = *(const uint32_t*)(brow + 64);
            const uint32_t bl01 = *(const uint32_t*)(brow + 80);
            const uint32_t bl10 = *(const uint32_t*)(brow + 96);
            const uint32_t bl11 = *(const uint32_t*)(brow + 112);

            float acc[8][4];
            #pragma unroll
            for (int g = 0; g < 8; g++) {
                acc[g][0] = 0.f; acc[g][1] = 0.f; acc[g][2] = 0.f; acc[g][3] = 0.f;
            }

            #pragma unroll
            for (int g = 0; g < 8; g++) {
                const char* ar0 = smc + SM_AS + (g * 128 + ftile + grp) * 144 + qid * 4;
                const char* ar1 = ar0 + 8 * 144;
                uint32_t a0, a1, a2, a3;
                a0 = *(const uint32_t*)(ar0);      a1 = *(const uint32_t*)(ar1);
                a2 = *(const uint32_t*)(ar0 + 16); a3 = *(const uint32_t*)(ar1 + 16);
                mma_bf16(acc[g], a0, a1, a2, a3, bh00, bh01);
                mma_bf16(acc[g], a0, a1, a2, a3, bl00, bl01);
                a0 = *(const uint32_t*)(ar0 + 32); a1 = *(const uint32_t*)(ar1 + 32);
                a2 = *(const uint32_t*)(ar0 + 48); a3 = *(const uint32_t*)(ar1 + 48);
                mma_bf16(acc[g], a0, a1, a2, a3, bh10, bh11);
                mma_bf16(acc[g], a0, a1, a2, a3, bl10, bl11);
                a0 = *(const uint32_t*)(ar0 + 64); a1 = *(const uint32_t*)(ar1 + 64);
                a2 = *(const uint32_t*)(ar0 + 80); a3 = *(const uint32_t*)(ar1 + 80);
                mma_bf16(acc[g], a0, a1, a2, a3, bh00, bh01);
                a0 = *(const uint32_t*)(ar0 + 96);  a1 = *(const uint32_t*)(ar1 + 96);
                a2 = *(const uint32_t*)(ar0 + 112); a3 = *(const uint32_t*)(ar1 + 112);
                mma_bf16(acc[g], a0, a1, a2, a3, bh10, bh11);
            }

            #pragma unroll
            for (int pf = 0; pf < 2; pf++) {
                const int fl = ftile + grp + pf * 8;
                float brf[8];
                #pragma unroll
                for (int g = 0; g < 8; g++) brf[g] = brs[g * 128 + fl];

                #pragma unroll
                for (int pe = 0; pe < 2; pe++) {
                    const int le  = esub + qid * 2 + pe;
                    const int pos = pf * 2 + pe;
                    const int nj  = jj[le];
                    const float fsv = fss[le];

                    const float* ph = g_phi + (size_t)nj * F8 + fl;
                    float x[8];
                    #pragma unroll
                    for (int g = 0; g < 8; g++)
                        x[g] = ph[g * 128] * (acc[g][pos] + brf[g] * fsv);

                    const float* vp = v + (size_t)nj * (3 * FD) + fl;
                    float vj0 = vp[0], vj1 = vp[FD], vj2 = vp[2 * FD];

                    const float* uu = us + le * 9;
                    float u1x = uu[0], u1y = uu[1], u1z = uu[2];
                    float u2x = uu[3], u2y = uu[4], u2z = uu[5];
                    float u3x = uu[6], u3y = uu[7], u3z = uu[8];

                    float dv0 = vj0 * x[1] + x[2] * u1x + x[3] * u2x + x[4] * u3x
                              + x[5] * (vj1 * u1z - vj2 * u1y)
                              + x[6] * (vj1 * u2z - vj2 * u2y)
                              + x[7] * (vj1 * u3z - vj2 * u3y);
                    float dv1 = vj1 * x[1] + x[2] * u1y + x[3] * u2y + x[4] * u3y
                              + x[5] * (vj2 * u1x - vj0 * u1z)
                              + x[6] * (vj2 * u2x - vj0 * u2z)
                              + x[7] * (vj2 * u3x - vj0 * u3z);
                    float dv2 = vj2 * x[1] + x[2] * u1z + x[3] * u2z + x[4] * u3z
                              + x[5] * (vj0 * u1y - vj1 * u1x)
                              + x[6] * (vj0 * u2y - vj1 * u2x)
                              + x[7] * (vj0 * u3y - vj1 * u3x);

                    const int ni = ii[le];
                    atomicAdd(out_s + (size_t)ni * FD + fl, x[0]);
                    float* ov = out_v + (size_t)ni * (3 * FD) + fl;
                    atomicAdd(ov,          dv0);
                    atomicAdd(ov + FD,     dv1);
                    atomicAdd(ov + 2 * FD, dv2);
                }
            }
        }

        // ---- C) STS prefetched data into next buffer ----
        if (do_next) {
            {
                int e = t >> 4;
                float v0 = p_r0 * p_f0 + p_r1 * p_f1 + p_r2 * p_f2;
                float v1 = p_r3 * p_f0 + p_r4 * p_f1 + p_r5 * p_f2;
                __nv_bfloat16 h0 = __float2bfloat16_rn(v0), h1 = __float2bfloat16_rn(v1);
                float l0 = v0 - __bfloat162float(h0), l1 = v1 - __bfloat162float(h1);
                char* rp = bnx + e * 144;
                __nv_bfloat162 hp = {h0, h1};
                *(uint32_t*)(rp + 4 * (t & 15))      = *(uint32_t*)&hp;
                *(uint32_t*)(rp + 64 + 4 * (t & 15)) = pack_bf16x2(l0, l1);
            }
            if (t < ET * 9) ((float*)(bnx + TB_US))[t] = p_u;
            if (t < ET) {
                ((float*)(bnx + TB_FSS))[t] = p_g1 + p_g2 + p_g3;
                ((int*)(bnx + TB_II))[t] = p_ii;
                ((int*)(bnx + TB_JJ))[t] = p_jj;
            }
        }

        // ---- D) single barrier per tile ----
        __syncthreads();
    }
}

// ===========================================================================
extern "C" void kernel_launch(void* const* d_in, const int* in_sizes, int n_in,
                              void* d_out, int out_size)
{
    const float* s    = (const float*)d_in[0];
    const float* v    = (const float*)d_in[1];
    const float* re1  = (const float*)d_in[2];
    const float* re2  = (const float*)d_in[3];
    const float* re3  = (const float*)d_in[4];
    const float* fc1  = (const float*)d_in[5];
    const float* fc2  = (const float*)d_in[6];
    const float* fc3  = (const float*)d_in[7];
    const float* u1   = (const float*)d_in[8];
    const float* u2   = (const float*)d_in[9];
    const float* u3   = (const float*)d_in[10];
    const int*   eidx = (const int*)d_in[11];
    const float* W1   = (const float*)d_in[12];
    const float* b1   = (const float*)d_in[13];
    const float* W2   = (const float*)d_in[14];
    const float* b2   = (const float*)d_in[15];
    const float* Wr   = (const float*)d_in[16];
    const float* br   = (const float*)d_in[17];

    float* out_s = (float*)d_out;
    float* out_v = out_s + (size_t)NN * FD;

    cudaFuncSetAttribute(phi_kernel,  cudaFuncAttributeMaxDynamicSharedMemorySize, PHI_SMEM);
    cudaFuncSetAttribute(edge_kernel, cudaFuncAttributeMaxDynamicSharedMemorySize, EDGE_SMEM);

    cudaMemcpyAsync(out_s, s, (size_t)NN * FD * sizeof(float),     cudaMemcpyDeviceToDevice, 0);
    cudaMemcpyAsync(out_v, v, (size_t)NN * 3 * FD * sizeof(float), cudaMemcpyDeviceToDevice, 0);

    phi_kernel<<<(NN + PHI_BM - 1) / PHI_BM, 256, PHI_SMEM>>>(s, W1, b1, W2, b2);

    edge_kernel<<<EGRID, 512, EDGE_SMEM>>>(re1, re2, re3, fc1, fc2, fc3,
                                           u1, u2, u3, eidx, Wr, br, v,
                                           out_s, out_v);
}

// round 15
// speedup vs baseline: 1.5959x; 1.0272x over previous
#include <cuda_runtime.h>
#include <cuda_bf16.h>
#include <cstdint>

#define NN 10000
#define NE 160000
#define FD 128
#define F8 1024

__device__ float g_phi[(size_t)NN * F8];

// ===========================================================================
// warp-level bf16 MMA (sm_80+ baseline — portable to compute_103)
// D[16 x 8] += A[16 x 16k] * B[16k x 8],  fp32 accumulate
// ===========================================================================
__device__ __forceinline__ void mma_bf16(float d[4],
    uint32_t a0, uint32_t a1, uint32_t a2, uint32_t a3,
    uint32_t b0, uint32_t b1)
{
    asm volatile(
        "mma.sync.aligned.m16n8k16.row.col.f32.bf16.bf16.f32 "
        "{%0,%1,%2,%3}, {%4,%5,%6,%7}, {%8,%9}, {%0,%1,%2,%3};\n"
        : "+f"(d[0]), "+f"(d[1]), "+f"(d[2]), "+f"(d[3])
        : "r"(a0), "r"(a1), "r"(a2), "r"(a3), "r"(b0), "r"(b1));
}

__device__ __forceinline__ uint32_t pack_bf16x2(float lo_val, float hi_val) {
    __nv_bfloat162 p = __floats2bfloat162_rn(lo_val, hi_val);
    return *(uint32_t*)&p;
}

// ===========================================================================
// phi = silu(s @ W1 + b1) @ W2 + b2    (unchanged from R14 — passing)
// ===========================================================================
#define PHI_BM 32
#define PHI_HA    0
#define PHI_W2T   17408
#define PHI_B2S   84992
#define PHI_SMEM  89088

__global__ __launch_bounds__(256) void phi_kernel(
    const float* __restrict__ s,
    const float* __restrict__ W1, const float* __restrict__ b1,
    const float* __restrict__ W2, const float* __restrict__ b2)
{
    extern __shared__ char smc[];
    float* A = (float*)smc;
    float* B = (float*)(smc + 16384);
    float* b2s = (float*)(smc + PHI_B2S);

    const int t = threadIdx.x;
    const int row0 = blockIdx.x * PHI_BM;
    const int tx = t & 31;
    const int ty = t >> 5;
    const int lane = t & 31;
    const int wid  = t >> 5;
    const int grp  = lane >> 2;
    const int qid  = lane & 3;

    for (int i = t; i < 1024; i += 256) b2s[i] = b2[i];

    {
        const float4* s4 = (const float4*)s;
        #pragma unroll
        for (int i = 0; i < 4; i++) {
            int idx = t + 256 * i;
            int r = idx >> 5;
            float4 val = make_float4(0.f, 0.f, 0.f, 0.f);
            if (row0 + r < NN) val = s4[(size_t)(row0 + r) * 32 + (idx & 31)];
            ((float4*)A)[idx] = val;
        }
        const float4* w4 = (const float4*)W1;
        #pragma unroll
        for (int i = 0; i < 16; i++)
            ((float4*)B)[t + 256 * i] = w4[t + 256 * i];
    }
    __syncthreads();

    float acc1[4][4];
    #pragma unroll
    for (int i = 0; i < 4; i++)
        #pragma unroll
        for (int j = 0; j < 4; j++) acc1[i][j] = 0.f;

    #pragma unroll 8
    for (int k = 0; k < FD; k++) {
        float4 bv = ((float4*)B)[k * 32 + tx];
        #pragma unroll
        for (int i = 0; i < 4; i++) {
            float a = A[(ty * 4 + i) * FD + k];
            acc1[i][0] += a * bv.x; acc1[i][1] += a * bv.y;
            acc1[i][2] += a * bv.z; acc1[i][3] += a * bv.w;
        }
    }
    float4 b1v = ((const float4*)b1)[tx];
    __syncthreads();

    #pragma unroll
    for (int i = 0; i < 4; i++) {
        float h[4];
        h[0] = acc1[i][0] + b1v.x; h[1] = acc1[i][1] + b1v.y;
        h[2] = acc1[i][2] + b1v.z; h[3] = acc1[i][3] + b1v.w;
        #pragma unroll
        for (int j = 0; j < 4; j++) h[j] = h[j] / (1.f + __expf(-h[j]));

        __nv_bfloat16 hh[4];
        float         hl[4];
        #pragma unroll
        for (int j = 0; j < 4; j++) {
            hh[j] = __float2bfloat16_rn(h[j]);
            hl[j] = h[j] - __bfloat162float(hh[j]);
        }
        char* rp = smc + PHI_HA + (ty * 4 + i) * 528;
        uint2 hiw, low;
        { __nv_bfloat162 p0 = {hh[0], hh[1]}, p1 = {hh[2], hh[3]};
          hiw.x = *(uint32_t*)&p0; hiw.y = *(uint32_t*)&p1; }
        low.x = pack_bf16x2(hl[0], hl[1]);
        low.y = pack_bf16x2(hl[2], hl[3]);
        *(uint2*)(rp + 8 * tx)       = hiw;
        *(uint2*)(rp + 256 + 8 * tx) = low;
    }
    __syncthreads();

    const int mtile = wid & 1;
    const int nbase = (wid >> 1) * 32;

    for (int g = 0; g < 8; g++) {
        #pragma unroll 4
        for (int q = 0; q < 32; q++) {
            int k = 4 * q + 2 * (t >> 7);
            int n = t & 127;
            float v0 = W2[(size_t)k * 1024 + g * 128 + n];
            float v1 = W2[(size_t)(k + 1) * 1024 + g * 128 + n];
            __nv_bfloat16 h0 = __float2bfloat16_rn(v0);
            __nv_bfloat16 h1 = __float2bfloat16_rn(v1);
            float l0 = v0 - __bfloat162float(h0);
            float l1 = v1 - __bfloat162float(h1);
            char* rp = smc + PHI_W2T + n * 528;
            __nv_bfloat162 hp = {h0, h1};
            *(uint32_t*)(rp + 2 * k)       = *(uint32_t*)&hp;
            *(uint32_t*)(rp + 256 + 2 * k) = pack_bf16x2(l0, l1);
        }
        __syncthreads();

        float acc[4][4];
        #pragma unroll
        for (int nt = 0; nt < 4; nt++) {
            acc[nt][0] = 0.f; acc[nt][1] = 0.f; acc[nt][2] = 0.f; acc[nt][3] = 0.f;
        }

        #pragma unroll
        for (int ks = 0; ks < 8; ks++) {
            const char* ar  = smc + PHI_HA + (mtile * 16 + grp) * 528 + ks * 32 + qid * 4;
            const char* ar8 = ar + 8 * 528;
            uint32_t ah0 = *(const uint32_t*)(ar);
            uint32_t ah1 = *(const uint32_t*)(ar8);
            uint32_t ah2 = *(const uint32_t*)(ar + 16);
            uint32_t ah3 = *(const uint32_t*)(ar8 + 16);
            uint32_t al0 = *(const uint32_t*)(ar + 256);
            uint32_t al1 = *(const uint32_t*)(ar8 + 256);
            uint32_t al2 = *(const uint32_t*)(ar + 272);
            uint32_t al3 = *(const uint32_t*)(ar8 + 272);
            #pragma unroll
            for (int nt = 0; nt < 4; nt++) {
                const char* brp = smc + PHI_W2T + (nbase + nt * 8 + grp) * 528 + ks * 32 + qid * 4;
                uint32_t bh0 = *(const uint32_t*)(brp);
                uint32_t bh1 = *(const uint32_t*)(brp + 16);
                uint32_t bl0 = *(const uint32_t*)(brp + 256);
                uint32_t bl1 = *(const uint32_t*)(brp + 272);
                mma_bf16(acc[nt], ah0, ah1, ah2, ah3, bh0, bh1);
                mma_bf16(acc[nt], ah0, ah1, ah2, ah3, bl0, bl1);
                mma_bf16(acc[nt], al0, al1, al2, al3, bh0, bh1);
            }
        }
        __syncthreads();

        #pragma unroll
        for (int nt = 0; nt < 4; nt++) {
            int n = nbase + nt * 8 + qid * 2;
            float bb0 = b2s[g * 128 + n], bb1 = b2s[g * 128 + n + 1];
            int r = row0 + mtile * 16 + grp;
            if (r < NN) {
                float2 o = make_float2(acc[nt][0] + bb0, acc[nt][1] + bb1);
                *(float2*)&g_phi[(size_t)r * 1024 + g * 128 + n] = o;
            }
            int r2 = r + 8;
            if (r2 < NN) {
                float2 o = make_float2(acc[nt][2] + bb0, acc[nt][3] + bb1);
                *(float2*)&g_phi[(size_t)r2 * 1024 + g * 128 + n] = o;
            }
        }
    }
}

// ===========================================================================
// Edge kernel R15 — operand-swapped mma: A = rc (resident frags), B = WrT.
// ET=16 edges/tile. Warp w = f-block w*8 (within every chunk), all 16 edges.
// Per g: 8 B-frag LDS + 6 mma, then x folded immediately into running
// (ds, dv0..2) per position. Double-buffered staging, 1 barrier/tile.
// Thread positions: e in {grp, grp+8}, f = fb*8 + 2qid + {0,1} (consecutive).
// ===========================================================================
#define ET 16
#define NT (NE / ET)    // 10000
#define EGRID 152

// smem byte offsets
#define SM_AS   0                        // WrT: 1024 rows x 144B = 147456
#define SM_BRS  147456                   // br: 4096
#define SM_T0   151552                   // tile buffer 0 (3072B)
#define SM_T1   154624                   // tile buffer 1
// tile buffer: rc 0..2303 (16 x 144B), us 2304..2879, fss 2880..2943,
//              ii 2944..3007, jj 3008..3071
#define TB_US   2304
#define TB_FSS  2880
#define TB_II   2944
#define TB_JJ   3008
#define EDGE_SMEM 157696

__global__ __launch_bounds__(512, 1) void edge_kernel(
    const float* __restrict__ re1, const float* __restrict__ re2, const float* __restrict__ re3,
    const float* __restrict__ fc1, const float* __restrict__ fc2, const float* __restrict__ fc3,
    const float* __restrict__ u1, const float* __restrict__ u2, const float* __restrict__ u3,
    const int* __restrict__ eidx,
    const float* __restrict__ Wr, const float* __restrict__ br,
    const float* __restrict__ v,
    float* __restrict__ out_s, float* __restrict__ out_v)
{
    extern __shared__ char smc[];
    const int t    = threadIdx.x;
    const int lane = t & 31;
    const int wid  = t >> 5;          // fb = wid: f-block of 8
    const int grp  = lane >> 2;
    const int qid  = lane & 3;
    const int f0   = wid * 8 + qid * 2;   // first of thread's f pair (in-chunk)

    float* brs = (float*)(smc + SM_BRS);

    // ---- stage WrT hi/lo into As, once per block ----
    #pragma unroll 4
    for (int i = 0; i < 64; i++) {
        int idx = t + 512 * i;           // 0..32767
        int k   = idx >> 10;
        int row = idx & 1023;
        float val = Wr[k * 1024 + row];
        __nv_bfloat16 hi = __float2bfloat16_rn(val);
        float lo = val - __bfloat162float(hi);
        char* rp = smc + SM_AS + row * 144;
        *(__nv_bfloat16*)(rp + 2 * k)      = hi;
        *(__nv_bfloat16*)(rp + 64 + 2 * k) = __float2bfloat16_rn(lo);
    }
    for (int i = t; i < 1024; i += 512) brs[i] = br[i];

    // ---- prologue: stage first tile into buf0 ----
    {
        char* bnx = smc + SM_T0;
        int e0n = blockIdx.x * ET;
        {
            int e = t >> 5, k = t & 31;      // 16 x 32
            int ge = e0n + e;
            float val = re1[ge * 32 + k] * fc1[ge]
                      + re2[ge * 32 + k] * fc2[ge]
                      + re3[ge * 32 + k] * fc3[ge];
            __nv_bfloat16 hi = __float2bfloat16_rn(val);
            float lo = val - __bfloat162float(hi);
            char* rp = bnx + e * 144;
            *(__nv_bfloat16*)(rp + 2 * k)      = hi;
            *(__nv_bfloat16*)(rp + 64 + 2 * k) = __float2bfloat16_rn(lo);
        }
        if (t < ET * 9) {
            int e = t / 9, c = t % 9;
            int ge = e0n + e;
            ((float*)(bnx + TB_US))[t] =
                  (c < 3) ? u1[ge * 3 + c]
                : (c < 6) ? u2[ge * 3 + (c - 3)]
                          : u3[ge * 3 + (c - 6)];
        }
        if (t < ET) {
            int ge = e0n + t;
            ((float*)(bnx + TB_FSS))[t] = fc1[ge] + fc2[ge] + fc3[ge];
            ((int*)(bnx + TB_II))[t] = eidx[ge];
            ((int*)(bnx + TB_JJ))[t] = eidx[NE + ge];
        }
    }
    __syncthreads();

    int iter = 0;
    for (int tile = blockIdx.x; tile < NT; tile += EGRID, iter++) {
        char* buf = smc + ((iter & 1) ? SM_T1 : SM_T0);
        char* bnx = smc + ((iter & 1) ? SM_T0 : SM_T1);
        const int tnext = tile + EGRID;
        const bool do_next = tnext < NT;

        // ---- A) issue prefetch LDGs for next tile ----
        float p_r0 = 0.f, p_r1 = 0.f, p_r2 = 0.f;
        float p_f0 = 0.f, p_f1 = 0.f, p_f2 = 0.f;
        float p_u = 0.f, p_g1 = 0.f, p_g2 = 0.f, p_g3 = 0.f;
        int   p_ii = 0, p_jj = 0;
        if (do_next) {
            int e0n = tnext * ET;
            {
                int e = t >> 5, k = t & 31;
                int ge = e0n + e;
                p_f0 = fc1[ge]; p_f1 = fc2[ge]; p_f2 = fc3[ge];
                p_r0 = re1[ge * 32 + k]; p_r1 = re2[ge * 32 + k]; p_r2 = re3[ge * 32 + k];
            }
            if (t < ET * 9) {
                int e = t / 9, c = t % 9;
                int ge = e0n + e;
                p_u = (c < 3) ? u1[ge * 3 + c]
                    : (c < 6) ? u2[ge * 3 + (c - 3)]
                              : u3[ge * 3 + (c - 6)];
            }
            if (t < ET) {
                int ge = e0n + t;
                p_g1 = fc1[ge]; p_g2 = fc2[ge]; p_g3 = fc3[ge];
                p_ii = eidx[ge]; p_jj = eidx[NE + ge];
            }
        }

        // ---- B) compute current tile ----
        const float* us  = (const float*)(buf + TB_US);
        const float* fss = (const float*)(buf + TB_FSS);
        const int*   ii  = (const int*)(buf + TB_II);
        const int*   jj  = (const int*)(buf + TB_JJ);

        // A fragments (rc): resident for the whole g-loop
        const char* ar  = buf + grp * 144 + qid * 4;
        const char* ar8 = ar + 8 * 144;
        const uint32_t ah0 = *(const uint32_t*)(ar);
        const uint32_t ah1 = *(const uint32_t*)(ar8);
        const uint32_t ah2 = *(const uint32_t*)(ar + 16);
        const uint32_t ah3 = *(const uint32_t*)(ar8 + 16);
        const uint32_t ah4 = *(const uint32_t*)(ar + 32);
        const uint32_t ah5 = *(const uint32_t*)(ar8 + 32);
        const uint32_t ah6 = *(const uint32_t*)(ar + 48);
        const uint32_t ah7 = *(const uint32_t*)(ar8 + 48);
        const uint32_t al0 = *(const uint32_t*)(ar + 64);
        const uint32_t al1 = *(const uint32_t*)(ar8 + 64);
        const uint32_t al2 = *(const uint32_t*)(ar + 80);
        const uint32_t al3 = *(const uint32_t*)(ar8 + 80);
        const uint32_t al4 = *(const uint32_t*)(ar + 96);
        const uint32_t al5 = *(const uint32_t*)(ar8 + 96);
        const uint32_t al6 = *(const uint32_t*)(ar + 112);
        const uint32_t al7 = *(const uint32_t*)(ar8 + 112);

        // per-edge data for the thread's two edges (e0 = grp, e1 = grp+8)
        const int e0 = grp, e1 = grp + 8;
        const int nj0 = jj[e0], nj1 = jj[e1];
        const int ni0 = ii[e0], ni1 = ii[e1];
        const float fs0 = fss[e0], fs1 = fss[e1];

        // vj float2 per (e, dim)
        const float* vp0 = v + (size_t)nj0 * (3 * FD) + f0;
        const float* vp1 = v + (size_t)nj1 * (3 * FD) + f0;
        const float2 vj00 = *(const float2*)(vp0);
        const float2 vj01 = *(const float2*)(vp0 + FD);
        const float2 vj02 = *(const float2*)(vp0 + 2 * FD);
        const float2 vj10 = *(const float2*)(vp1);
        const float2 vj11 = *(const float2*)(vp1 + FD);
        const float2 vj12 = *(const float2*)(vp1 + 2 * FD);

        // u per edge (9 each)
        float uA[9], uB[9];
        #pragma unroll
        for (int c = 0; c < 9; c++) { uA[c] = us[e0 * 9 + c]; uB[c] = us[e1 * 9 + c]; }

        // running outputs: [e][f-pair]
        float ds00 = 0.f, ds01 = 0.f, ds10 = 0.f, ds11 = 0.f;
        float dv000 = 0.f, dv001 = 0.f, dv010 = 0.f, dv011 = 0.f, dv020 = 0.f, dv021 = 0.f;
        float dv100 = 0.f, dv101 = 0.f, dv110 = 0.f, dv111 = 0.f, dv120 = 0.f, dv121 = 0.f;

        const float* ph0b = g_phi + (size_t)nj0 * F8 + f0;
        const float* ph1b = g_phi + (size_t)nj1 * F8 + f0;

        #pragma unroll
        for (int g = 0; g < 8; g++) {
            // B fragments (WrT) for (g, f-block)
            const char* brp = smc + SM_AS + (g * 128 + wid * 8 + grp) * 144 + qid * 4;
            const uint32_t bh0 = *(const uint32_t*)(brp);
            const uint32_t bh1 = *(const uint32_t*)(brp + 16);
            const uint32_t bh2 = *(const uint32_t*)(brp + 32);
            const uint32_t bh3 = *(const uint32_t*)(brp + 48);
            const uint32_t bl0 = *(const uint32_t*)(brp + 64);
            const uint32_t bl1 = *(const uint32_t*)(brp + 80);
            const uint32_t bl2 = *(const uint32_t*)(brp + 96);
            const uint32_t bl3 = *(const uint32_t*)(brp + 112);

            float acc[4] = {0.f, 0.f, 0.f, 0.f};
            mma_bf16(acc, ah0, ah1, ah2, ah3, bh0, bh1);   // hi*hi ks0
            mma_bf16(acc, ah4, ah5, ah6, ah7, bh2, bh3);   // hi*hi ks1
            mma_bf16(acc, ah0, ah1, ah2, ah3, bl0, bl1);   // Ahi*Blo ks0
            mma_bf16(acc, ah4, ah5, ah6, ah7, bl2, bl3);   // Ahi*Blo ks1
            mma_bf16(acc, al0, al1, al2, al3, bh0, bh1);   // Alo*Bhi ks0
            mma_bf16(acc, al4, al5, al6, al7, bh2, bh3);   // Alo*Bhi ks1

            const float2 brf = *(const float2*)&brs[g * 128 + f0];
            const float2 ph0 = *(const float2*)(ph0b + g * 128);
            const float2 ph1 = *(const float2*)(ph1b + g * 128);

            const float x00 = ph0.x * (acc[0] + brf.x * fs0);
            const float x01 = ph0.y * (acc[1] + brf.y * fs0);
            const float x10 = ph1.x * (acc[2] + brf.x * fs1);
            const float x11 = ph1.y * (acc[3] + brf.y * fs1);

            if (g == 0) {
                ds00 += x00; ds01 += x01; ds10 += x10; ds11 += x11;
            } else if (g == 1) {
                dv000 += vj00.x * x00; dv001 += vj00.y * x01;
                dv010 += vj01.x * x00; dv011 += vj01.y * x01;
                dv020 += vj02.x * x00; dv021 += vj02.y * x01;
                dv100 += vj10.x * x10; dv101 += vj10.y * x11;
                dv110 += vj11.x * x10; dv111 += vj11.y * x11;
                dv120 += vj12.x * x10; dv121 += vj12.y * x11;
            } else if (g <= 4) {
                const int k3 = (g - 2) * 3;
                dv000 += uA[k3] * x00;     dv001 += uA[k3] * x01;
                dv010 += uA[k3 + 1] * x00; dv011 += uA[k3 + 1] * x01;
                dv020 += uA[k3 + 2] * x00; dv021 += uA[k3 + 2] * x01;
                dv100 += uB[k3] * x10;     dv101 += uB[k3] * x11;
                dv110 += uB[k3 + 1] * x10; dv111 += uB[k3 + 1] * x11;
                dv120 += uB[k3 + 2] * x10; dv121 += uB[k3 + 2] * x11;
            } else {
                const int k3 = (g - 5) * 3;
                const float ax = uA[k3], ay = uA[k3 + 1], az = uA[k3 + 2];
                dv000 += (vj01.x * az - vj02.x * ay) * x00;
                dv001 += (vj01.y * az - vj02.y * ay) * x01;
                dv010 += (vj02.x * ax - vj00.x * az) * x00;
                dv011 += (vj02.y * ax - vj00.y * az) * x01;
                dv020 += (vj00.x * ay - vj01.x * ax) * x00;
                dv021 += (vj00.y * ay - vj01.y * ax) * x01;
                const float bx = uB[k3], by = uB[k3 + 1], bz = uB[k3 + 2];
                dv100 += (vj11.x * bz - vj12.x * by) * x10;
                dv101 += (vj11.y * bz - vj12.y * by) * x11;
                dv110 += (vj12.x * bx - vj10.x * bz) * x10;
                dv111 += (vj12.y * bx - vj10.y * bz) * x11;
                dv120 += (vj10.x * by - vj11.x * bx) * x10;
                dv121 += (vj10.y * by - vj11.y * bx) * x11;
            }
        }

        // ---- final scatter: 16 atomics ----
        {
            float* os0 = out_s + (size_t)ni0 * FD + f0;
            atomicAdd(os0,     ds00);
            atomicAdd(os0 + 1, ds01);
            float* ov0 = out_v + (size_t)ni0 * (3 * FD) + f0;
            atomicAdd(ov0,              dv000);
            atomicAdd(ov0 + 1,          dv001);
            atomicAdd(ov0 + FD,         dv010);
            atomicAdd(ov0 + FD + 1,     dv011);
            atomicAdd(ov0 + 2 * FD,     dv020);
            atomicAdd(ov0 + 2 * FD + 1, dv021);

            float* os1 = out_s + (size_t)ni1 * FD + f0;
            atomicAdd(os1,     ds10);
            atomicAdd(os1 + 1, ds11);
            float* ov1 = out_v + (size_t)ni1 * (3 * FD) + f0;
            atomicAdd(ov1,              dv100);
            atomicAdd(ov1 + 1,          dv101);
            atomicAdd(ov1 + FD,         dv110);
            atomicAdd(ov1 + FD + 1,     dv111);
            atomicAdd(ov1 + 2 * FD,     dv120);
            atomicAdd(ov1 + 2 * FD + 1, dv121);
        }

        // ---- C) STS prefetched data into next buffer ----
        if (do_next) {
            {
                int e = t >> 5, k = t & 31;
                float val = p_r0 * p_f0 + p_r1 * p_f1 + p_r2 * p_f2;
                __nv_bfloat16 hi = __float2bfloat16_rn(val);
                float lo = val - __bfloat162float(hi);
                char* rp = bnx + e * 144;
                *(__nv_bfloat16*)(rp + 2 * k)      = hi;
                *(__nv_bfloat16*)(rp + 64 + 2 * k) = __float2bfloat16_rn(lo);
            }
            if (t < ET * 9) ((float*)(bnx + TB_US))[t] = p_u;
            if (t < ET) {
                ((float*)(bnx + TB_FSS))[t] = p_g1 + p_g2 + p_g3;
                ((int*)(bnx + TB_II))[t] = p_ii;
                ((int*)(bnx + TB_JJ))[t] = p_jj;
            }
        }

        // ---- D) single barrier per tile ----
        __syncthreads();
    }
}

// ===========================================================================
extern "C" void kernel_launch(void* const* d_in, const int* in_sizes, int n_in,
                              void* d_out, int out_size)
{
    const float* s    = (const float*)d_in[0];
    const float* v    = (const float*)d_in[1];
    const float* re1  = (const float*)d_in[2];
    const float* re2  = (const float*)d_in[3];
    const float* re3  = (const float*)d_in[4];
    const float* fc1  = (const float*)d_in[5];
    const float* fc2  = (const float*)d_in[6];
    const float* fc3  = (const float*)d_in[7];
    const float* u1   = (const float*)d_in[8];
    const float* u2   = (const float*)d_in[9];
    const float* u3   = (const float*)d_in[10];
    const int*   eidx = (const int*)d_in[11];
    const float* W1   = (const float*)d_in[12];
    const float* b1   = (const float*)d_in[13];
    const float* W2   = (const float*)d_in[14];
    const float* b2   = (const float*)d_in[15];
    const float* Wr   = (const float*)d_in[16];
    const float* br   = (const float*)d_in[17];

    float* out_s = (float*)d_out;
    float* out_v = out_s + (size_t)NN * FD;

    cudaFuncSetAttribute(phi_kernel,  cudaFuncAttributeMaxDynamicSharedMemorySize, PHI_SMEM);
    cudaFuncSetAttribute(edge_kernel, cudaFuncAttributeMaxDynamicSharedMemorySize, EDGE_SMEM);

    cudaMemcpyAsync(out_s, s, (size_t)NN * FD * sizeof(float),     cudaMemcpyDeviceToDevice, 0);
    cudaMemcpyAsync(out_v, v, (size_t)NN * 3 * FD * sizeof(float), cudaMemcpyDeviceToDevice, 0);

    phi_kernel<<<(NN + PHI_BM - 1) / PHI_BM, 256, PHI_SMEM>>>(s, W1, b1, W2, b2);

    edge_kernel<<<EGRID, 512, EDGE_SMEM>>>(re1, re2, re3, fc1, fc2, fc3,
                                           u1, u2, u3, eidx, Wr, br, v,
                                           out_s, out_v);
}

// round 16
// speedup vs baseline: 1.7221x; 1.0791x over previous
#include <cuda_runtime.h>
#include <cuda_bf16.h>
#include <cstdint>

#define NN 10000
#define NE 160000
#define FD 128
#define F8 1024

__device__ float g_phi[(size_t)NN * F8];

// ===========================================================================
// warp-level bf16 MMA (sm_80+ baseline — portable to compute_103)
// ===========================================================================
__device__ __forceinline__ void mma_bf16(float d[4],
    uint32_t a0, uint32_t a1, uint32_t a2, uint32_t a3,
    uint32_t b0, uint32_t b1)
{
    asm volatile(
        "mma.sync.aligned.m16n8k16.row.col.f32.bf16.bf16.f32 "
        "{%0,%1,%2,%3}, {%4,%5,%6,%7}, {%8,%9}, {%0,%1,%2,%3};\n"
        : "+f"(d[0]), "+f"(d[1]), "+f"(d[2]), "+f"(d[3])
        : "r"(a0), "r"(a1), "r"(a2), "r"(a3), "r"(b0), "r"(b1));
}

__device__ __forceinline__ uint32_t pack_bf16x2(float lo_val, float hi_val) {
    __nv_bfloat162 p = __floats2bfloat162_rn(lo_val, hi_val);
    return *(uint32_t*)&p;
}

// Non-returning vector atomic add: one L1 op for two consecutive floats.
// PTX ISA 8.1+, sm_90+ baseline feature (valid under compute_103).
__device__ __forceinline__ void red_add_v2(float* p, float a, float b) {
    asm volatile("red.global.add.v2.f32 [%0], {%1, %2};"
                 :: "l"(p), "f"(a), "f"(b) : "memory");
}

// ===========================================================================
// phi = silu(s @ W1 + b1) @ W2 + b2    (unchanged from R14/R15 — passing)
// ===========================================================================
#define PHI_BM 32
#define PHI_HA    0
#define PHI_W2T   17408
#define PHI_B2S   84992
#define PHI_SMEM  89088

__global__ __launch_bounds__(256) void phi_kernel(
    const float* __restrict__ s,
    const float* __restrict__ W1, const float* __restrict__ b1,
    const float* __restrict__ W2, const float* __restrict__ b2)
{
    extern __shared__ char smc[];
    float* A = (float*)smc;
    float* B = (float*)(smc + 16384);
    float* b2s = (float*)(smc + PHI_B2S);

    const int t = threadIdx.x;
    const int row0 = blockIdx.x * PHI_BM;
    const int tx = t & 31;
    const int ty = t >> 5;
    const int lane = t & 31;
    const int wid  = t >> 5;
    const int grp  = lane >> 2;
    const int qid  = lane & 3;

    for (int i = t; i < 1024; i += 256) b2s[i] = b2[i];

    {
        const float4* s4 = (const float4*)s;
        #pragma unroll
        for (int i = 0; i < 4; i++) {
            int idx = t + 256 * i;
            int r = idx >> 5;
            float4 val = make_float4(0.f, 0.f, 0.f, 0.f);
            if (row0 + r < NN) val = s4[(size_t)(row0 + r) * 32 + (idx & 31)];
            ((float4*)A)[idx] = val;
        }
        const float4* w4 = (const float4*)W1;
        #pragma unroll
        for (int i = 0; i < 16; i++)
            ((float4*)B)[t + 256 * i] = w4[t + 256 * i];
    }
    __syncthreads();

    float acc1[4][4];
    #pragma unroll
    for (int i = 0; i < 4; i++)
        #pragma unroll
        for (int j = 0; j < 4; j++) acc1[i][j] = 0.f;

    #pragma unroll 8
    for (int k = 0; k < FD; k++) {
        float4 bv = ((float4*)B)[k * 32 + tx];
        #pragma unroll
        for (int i = 0; i < 4; i++) {
            float a = A[(ty * 4 + i) * FD + k];
            acc1[i][0] += a * bv.x; acc1[i][1] += a * bv.y;
            acc1[i][2] += a * bv.z; acc1[i][3] += a * bv.w;
        }
    }
    float4 b1v = ((const float4*)b1)[tx];
    __syncthreads();

    #pragma unroll
    for (int i = 0; i < 4; i++) {
        float h[4];
        h[0] = acc1[i][0] + b1v.x; h[1] = acc1[i][1] + b1v.y;
        h[2] = acc1[i][2] + b1v.z; h[3] = acc1[i][3] + b1v.w;
        #pragma unroll
        for (int j = 0; j < 4; j++) h[j] = h[j] / (1.f + __expf(-h[j]));

        __nv_bfloat16 hh[4];
        float         hl[4];
        #pragma unroll
        for (int j = 0; j < 4; j++) {
            hh[j] = __float2bfloat16_rn(h[j]);
            hl[j] = h[j] - __bfloat162float(hh[j]);
        }
        char* rp = smc + PHI_HA + (ty * 4 + i) * 528;
        uint2 hiw, low;
        { __nv_bfloat162 p0 = {hh[0], hh[1]}, p1 = {hh[2], hh[3]};
          hiw.x = *(uint32_t*)&p0; hiw.y = *(uint32_t*)&p1; }
        low.x = pack_bf16x2(hl[0], hl[1]);
        low.y = pack_bf16x2(hl[2], hl[3]);
        *(uint2*)(rp + 8 * tx)       = hiw;
        *(uint2*)(rp + 256 + 8 * tx) = low;
    }
    __syncthreads();

    const int mtile = wid & 1;
    const int nbase = (wid >> 1) * 32;

    for (int g = 0; g < 8; g++) {
        #pragma unroll 4
        for (int q = 0; q < 32; q++) {
            int k = 4 * q + 2 * (t >> 7);
            int n = t & 127;
            float v0 = W2[(size_t)k * 1024 + g * 128 + n];
            float v1 = W2[(size_t)(k + 1) * 1024 + g * 128 + n];
            __nv_bfloat16 h0 = __float2bfloat16_rn(v0);
            __nv_bfloat16 h1 = __float2bfloat16_rn(v1);
            float l0 = v0 - __bfloat162float(h0);
            float l1 = v1 - __bfloat162float(h1);
            char* rp = smc + PHI_W2T + n * 528;
            __nv_bfloat162 hp = {h0, h1};
            *(uint32_t*)(rp + 2 * k)       = *(uint32_t*)&hp;
            *(uint32_t*)(rp + 256 + 2 * k) = pack_bf16x2(l0, l1);
        }
        __syncthreads();

        float acc[4][4];
        #pragma unroll
        for (int nt = 0; nt < 4; nt++) {
            acc[nt][0] = 0.f; acc[nt][1] = 0.f; acc[nt][2] = 0.f; acc[nt][3] = 0.f;
        }

        #pragma unroll
        for (int ks = 0; ks < 8; ks++) {
            const char* ar  = smc + PHI_HA + (mtile * 16 + grp) * 528 + ks * 32 + qid * 4;
            const char* ar8 = ar + 8 * 528;
            uint32_t ah0 = *(const uint32_t*)(ar);
            uint32_t ah1 = *(const uint32_t*)(ar8);
            uint32_t ah2 = *(const uint32_t*)(ar + 16);
            uint32_t ah3 = *(const uint32_t*)(ar8 + 16);
            uint32_t al0 = *(const uint32_t*)(ar + 256);
            uint32_t al1 = *(const uint32_t*)(ar8 + 256);
            uint32_t al2 = *(const uint32_t*)(ar + 272);
            uint32_t al3 = *(const uint32_t*)(ar8 + 272);
            #pragma unroll
            for (int nt = 0; nt < 4; nt++) {
                const char* brp = smc + PHI_W2T + (nbase + nt * 8 + grp) * 528 + ks * 32 + qid * 4;
                uint32_t bh0 = *(const uint32_t*)(brp);
                uint32_t bh1 = *(const uint32_t*)(brp + 16);
                uint32_t bl0 = *(const uint32_t*)(brp + 256);
                uint32_t bl1 = *(const uint32_t*)(brp + 272);
                mma_bf16(acc[nt], ah0, ah1, ah2, ah3, bh0, bh1);
                mma_bf16(acc[nt], ah0, ah1, ah2, ah3, bl0, bl1);
                mma_bf16(acc[nt], al0, al1, al2, al3, bh0, bh1);
            }
        }
        __syncthreads();

        #pragma unroll
        for (int nt = 0; nt < 4; nt++) {
            int n = nbase + nt * 8 + qid * 2;
            float bb0 = b2s[g * 128 + n], bb1 = b2s[g * 128 + n + 1];
            int r = row0 + mtile * 16 + grp;
            if (r < NN) {
                float2 o = make_float2(acc[nt][0] + bb0, acc[nt][1] + bb1);
                *(float2*)&g_phi[(size_t)r * 1024 + g * 128 + n] = o;
            }
            int r2 = r + 8;
            if (r2 < NN) {
                float2 o = make_float2(acc[nt][2] + bb0, acc[nt][3] + bb1);
                *(float2*)&g_phi[(size_t)r2 * 1024 + g * 128 + n] = o;
            }
        }
    }
}

// ===========================================================================
// Edge kernel R16 — R15 structure, epilogue scatter via red.global.add.v2.f32
// (8 vector reds per thread per tile instead of 16 scalar atomicAdds).
// ===========================================================================
#define ET 16
#define NT (NE / ET)    // 10000
#define EGRID 152

#define SM_AS   0                        // WrT: 1024 rows x 144B = 147456
#define SM_BRS  147456                   // br: 4096
#define SM_T0   151552                   // tile buffer 0 (3072B)
#define SM_T1   154624                   // tile buffer 1
#define TB_US   2304
#define TB_FSS  2880
#define TB_II   2944
#define TB_JJ   3008
#define EDGE_SMEM 157696

__global__ __launch_bounds__(512, 1) void edge_kernel(
    const float* __restrict__ re1, const float* __restrict__ re2, const float* __restrict__ re3,
    const float* __restrict__ fc1, const float* __restrict__ fc2, const float* __restrict__ fc3,
    const float* __restrict__ u1, const float* __restrict__ u2, const float* __restrict__ u3,
    const int* __restrict__ eidx,
    const float* __restrict__ Wr, const float* __restrict__ br,
    const float* __restrict__ v,
    float* __restrict__ out_s, float* __restrict__ out_v)
{
    extern __shared__ char smc[];
    const int t    = threadIdx.x;
    const int lane = t & 31;
    const int wid  = t >> 5;
    const int grp  = lane >> 2;
    const int qid  = lane & 3;
    const int f0   = wid * 8 + qid * 2;

    float* brs = (float*)(smc + SM_BRS);

    // ---- stage WrT hi/lo into As, once per block ----
    #pragma unroll 4
    for (int i = 0; i < 64; i++) {
        int idx = t + 512 * i;
        int k   = idx >> 10;
        int row = idx & 1023;
        float val = Wr[k * 1024 + row];
        __nv_bfloat16 hi = __float2bfloat16_rn(val);
        float lo = val - __bfloat162float(hi);
        char* rp = smc + SM_AS + row * 144;
        *(__nv_bfloat16*)(rp + 2 * k)      = hi;
        *(__nv_bfloat16*)(rp + 64 + 2 * k) = __float2bfloat16_rn(lo);
    }
    for (int i = t; i < 1024; i += 512) brs[i] = br[i];

    // ---- prologue: stage first tile into buf0 ----
    {
        char* bnx = smc + SM_T0;
        int e0n = blockIdx.x * ET;
        {
            int e = t >> 5, k = t & 31;
            int ge = e0n + e;
            float val = re1[ge * 32 + k] * fc1[ge]
                      + re2[ge * 32 + k] * fc2[ge]
                      + re3[ge * 32 + k] * fc3[ge];
            __nv_bfloat16 hi = __float2bfloat16_rn(val);
            float lo = val - __bfloat162float(hi);
            char* rp = bnx + e * 144;
            *(__nv_bfloat16*)(rp + 2 * k)      = hi;
            *(__nv_bfloat16*)(rp + 64 + 2 * k) = __float2bfloat16_rn(lo);
        }
        if (t < ET * 9) {
            int e = t / 9, c = t % 9;
            int ge = e0n + e;
            ((float*)(bnx + TB_US))[t] =
                  (c < 3) ? u1[ge * 3 + c]
                : (c < 6) ? u2[ge * 3 + (c - 3)]
                          : u3[ge * 3 + (c - 6)];
        }
        if (t < ET) {
            int ge = e0n + t;
            ((float*)(bnx + TB_FSS))[t] = fc1[ge] + fc2[ge] + fc3[ge];
            ((int*)(bnx + TB_II))[t] = eidx[ge];
            ((int*)(bnx + TB_JJ))[t] = eidx[NE + ge];
        }
    }
    __syncthreads();

    int iter = 0;
    for (int tile = blockIdx.x; tile < NT; tile += EGRID, iter++) {
        char* buf = smc + ((iter & 1) ? SM_T1 : SM_T0);
        char* bnx = smc + ((iter & 1) ? SM_T0 : SM_T1);
        const int tnext = tile + EGRID;
        const bool do_next = tnext < NT;

        // ---- A) prefetch LDGs for next tile ----
        float p_r0 = 0.f, p_r1 = 0.f, p_r2 = 0.f;
        float p_f0 = 0.f, p_f1 = 0.f, p_f2 = 0.f;
        float p_u = 0.f, p_g1 = 0.f, p_g2 = 0.f, p_g3 = 0.f;
        int   p_ii = 0, p_jj = 0;
        if (do_next) {
            int e0n = tnext * ET;
            {
                int e = t >> 5, k = t & 31;
                int ge = e0n + e;
                p_f0 = fc1[ge]; p_f1 = fc2[ge]; p_f2 = fc3[ge];
                p_r0 = re1[ge * 32 + k]; p_r1 = re2[ge * 32 + k]; p_r2 = re3[ge * 32 + k];
            }
            if (t < ET * 9) {
                int e = t / 9, c = t % 9;
                int ge = e0n + e;
                p_u = (c < 3) ? u1[ge * 3 + c]
                    : (c < 6) ? u2[ge * 3 + (c - 3)]
                              : u3[ge * 3 + (c - 6)];
            }
            if (t < ET) {
                int ge = e0n + t;
                p_g1 = fc1[ge]; p_g2 = fc2[ge]; p_g3 = fc3[ge];
                p_ii = eidx[ge]; p_jj = eidx[NE + ge];
            }
        }

        // ---- B) compute current tile ----
        const float* us  = (const float*)(buf + TB_US);
        const float* fss = (const float*)(buf + TB_FSS);
        const int*   ii  = (const int*)(buf + TB_II);
        const int*   jj  = (const int*)(buf + TB_JJ);

        const char* ar  = buf + grp * 144 + qid * 4;
        const char* ar8 = ar + 8 * 144;
        const uint32_t ah0 = *(const uint32_t*)(ar);
        const uint32_t ah1 = *(const uint32_t*)(ar8);
        const uint32_t ah2 = *(const uint32_t*)(ar + 16);
        const uint32_t ah3 = *(const uint32_t*)(ar8 + 16);
        const uint32_t ah4 = *(const uint32_t*)(ar + 32);
        const uint32_t ah5 = *(const uint32_t*)(ar8 + 32);
        const uint32_t ah6 = *(const uint32_t*)(ar + 48);
        const uint32_t ah7 = *(const uint32_t*)(ar8 + 48);
        const uint32_t al0 = *(const uint32_t*)(ar + 64);
        const uint32_t al1 = *(const uint32_t*)(ar8 + 64);
        const uint32_t al2 = *(const uint32_t*)(ar + 80);
        const uint32_t al3 = *(const uint32_t*)(ar8 + 80);
        const uint32_t al4 = *(const uint32_t*)(ar + 96);
        const uint32_t al5 = *(const uint32_t*)(ar8 + 96);
        const uint32_t al6 = *(const uint32_t*)(ar + 112);
        const uint32_t al7 = *(const uint32_t*)(ar8 + 112);

        const int e0 = grp, e1 = grp + 8;
        const int nj0 = jj[e0], nj1 = jj[e1];
        const int ni0 = ii[e0], ni1 = ii[e1];
        const float fs0 = fss[e0], fs1 = fss[e1];

        const float* vp0 = v + (size_t)nj0 * (3 * FD) + f0;
        const float* vp1 = v + (size_t)nj1 * (3 * FD) + f0;
        const float2 vj00 = *(const float2*)(vp0);
        const float2 vj01 = *(const float2*)(vp0 + FD);
        const float2 vj02 = *(const float2*)(vp0 + 2 * FD);
        const float2 vj10 = *(const float2*)(vp1);
        const float2 vj11 = *(const float2*)(vp1 + FD);
        const float2 vj12 = *(const float2*)(vp1 + 2 * FD);

        float uA[9], uB[9];
        #pragma unroll
        for (int c = 0; c < 9; c++) { uA[c] = us[e0 * 9 + c]; uB[c] = us[e1 * 9 + c]; }

        float ds00 = 0.f, ds01 = 0.f, ds10 = 0.f, ds11 = 0.f;
        float dv000 = 0.f, dv001 = 0.f, dv010 = 0.f, dv011 = 0.f, dv020 = 0.f, dv021 = 0.f;
        float dv100 = 0.f, dv101 = 0.f, dv110 = 0.f, dv111 = 0.f, dv120 = 0.f, dv121 = 0.f;

        const float* ph0b = g_phi + (size_t)nj0 * F8 + f0;
        const float* ph1b = g_phi + (size_t)nj1 * F8 + f0;

        #pragma unroll
        for (int g = 0; g < 8; g++) {
            const char* brp = smc + SM_AS + (g * 128 + wid * 8 + grp) * 144 + qid * 4;
            const uint32_t bh0 = *(const uint32_t*)(brp);
            const uint32_t bh1 = *(const uint32_t*)(brp + 16);
            const uint32_t bh2 = *(const uint32_t*)(brp + 32);
            const uint32_t bh3 = *(const uint32_t*)(brp + 48);
            const uint32_t bl0 = *(const uint32_t*)(brp + 64);
            const uint32_t bl1 = *(const uint32_t*)(brp + 80);
            const uint32_t bl2 = *(const uint32_t*)(brp + 96);
            const uint32_t bl3 = *(const uint32_t*)(brp + 112);

            float acc[4] = {0.f, 0.f, 0.f, 0.f};
            mma_bf16(acc, ah0, ah1, ah2, ah3, bh0, bh1);
            mma_bf16(acc, ah4, ah5, ah6, ah7, bh2, bh3);
            mma_bf16(acc, ah0, ah1, ah2, ah3, bl0, bl1);
            mma_bf16(acc, ah4, ah5, ah6, ah7, bl2, bl3);
            mma_bf16(acc, al0, al1, al2, al3, bh0, bh1);
            mma_bf16(acc, al4, al5, al6, al7, bh2, bh3);

            const float2 brf = *(const float2*)&brs[g * 128 + f0];
            const float2 ph0 = *(const float2*)(ph0b + g * 128);
            const float2 ph1 = *(const float2*)(ph1b + g * 128);

            const float x00 = ph0.x * (acc[0] + brf.x * fs0);
            const float x01 = ph0.y * (acc[1] + brf.y * fs0);
            const float x10 = ph1.x * (acc[2] + brf.x * fs1);
            const float x11 = ph1.y * (acc[3] + brf.y * fs1);

            if (g == 0) {
                ds00 += x00; ds01 += x01; ds10 += x10; ds11 += x11;
            } else if (g == 1) {
                dv000 += vj00.x * x00; dv001 += vj00.y * x01;
                dv010 += vj01.x * x00; dv011 += vj01.y * x01;
                dv020 += vj02.x * x00; dv021 += vj02.y * x01;
                dv100 += vj10.x * x10; dv101 += vj10.y * x11;
                dv110 += vj11.x * x10; dv111 += vj11.y * x11;
                dv120 += vj12.x * x10; dv121 += vj12.y * x11;
            } else if (g <= 4) {
                const int k3 = (g - 2) * 3;
                dv000 += uA[k3] * x00;     dv001 += uA[k3] * x01;
                dv010 += uA[k3 + 1] * x00; dv011 += uA[k3 + 1] * x01;
                dv020 += uA[k3 + 2] * x00; dv021 += uA[k3 + 2] * x01;
                dv100 += uB[k3] * x10;     dv101 += uB[k3] * x11;
                dv110 += uB[k3 + 1] * x10; dv111 += uB[k3 + 1] * x11;
                dv120 += uB[k3 + 2] * x10; dv121 += uB[k3 + 2] * x11;
            } else {
                const int k3 = (g - 5) * 3;
                const float ax = uA[k3], ay = uA[k3 + 1], az = uA[k3 + 2];
                dv000 += (vj01.x * az - vj02.x * ay) * x00;
                dv001 += (vj01.y * az - vj02.y * ay) * x01;
                dv010 += (vj02.x * ax - vj00.x * az) * x00;
                dv011 += (vj02.y * ax - vj00.y * az) * x01;
                dv020 += (vj00.x * ay - vj01.x * ax) * x00;
                dv021 += (vj00.y * ay - vj01.y * ax) * x01;
                const float bx = uB[k3], by = uB[k3 + 1], bz = uB[k3 + 2];
                dv100 += (vj11.x * bz - vj12.x * by) * x10;
                dv101 += (vj11.y * bz - vj12.y * by) * x11;
                dv110 += (vj12.x * bx - vj10.x * bz) * x10;
                dv111 += (vj12.y * bx - vj10.y * bz) * x11;
                dv120 += (vj10.x * by - vj11.x * bx) * x10;
                dv121 += (vj10.y * by - vj11.y * bx) * x11;
            }
        }

        // ---- final scatter: 8 vector reds (was 16 scalar atomics) ----
        {
            red_add_v2(out_s + (size_t)ni0 * FD + f0, ds00, ds01);
            float* ov0 = out_v + (size_t)ni0 * (3 * FD) + f0;
            red_add_v2(ov0,          dv000, dv001);
            red_add_v2(ov0 + FD,     dv010, dv011);
            red_add_v2(ov0 + 2 * FD, dv020, dv021);

            red_add_v2(out_s + (size_t)ni1 * FD + f0, ds10, ds11);
            float* ov1 = out_v + (size_t)ni1 * (3 * FD) + f0;
            red_add_v2(ov1,          dv100, dv101);
            red_add_v2(ov1 + FD,     dv110, dv111);
            red_add_v2(ov1 + 2 * FD, dv120, dv121);
        }

        // ---- C) STS prefetched data into next buffer ----
        if (do_next) {
            {
                int e = t >> 5, k = t & 31;
                float val = p_r0 * p_f0 + p_r1 * p_f1 + p_r2 * p_f2;
                __nv_bfloat16 hi = __float2bfloat16_rn(val);
                float lo = val - __bfloat162float(hi);
                char* rp = bnx + e * 144;
                *(__nv_bfloat16*)(rp + 2 * k)      = hi;
                *(__nv_bfloat16*)(rp + 64 + 2 * k) = __float2bfloat16_rn(lo);
            }
            if (t < ET * 9) ((float*)(bnx + TB_US))[t] = p_u;
            if (t < ET) {
                ((float*)(bnx + TB_FSS))[t] = p_g1 + p_g2 + p_g3;
                ((int*)(bnx + TB_II))[t] = p_ii;
                ((int*)(bnx + TB_JJ))[t] = p_jj;
            }
        }

        // ---- D) single barrier per tile ----
        __syncthreads();
    }
}

// ===========================================================================
extern "C" void kernel_launch(void* const* d_in, const int* in_sizes, int n_in,
                              void* d_out, int out_size)
{
    const float* s    = (const float*)d_in[0];
    const float* v    = (const float*)d_in[1];
    const float* re1  = (const float*)d_in[2];
    const float* re2  = (const float*)d_in[3];
    const float* re3  = (const float*)d_in[4];
    const float* fc1  = (const float*)d_in[5];
    const float* fc2  = (const float*)d_in[6];
    const float* fc3  = (const float*)d_in[7];
    const float* u1   = (const float*)d_in[8];
    const float* u2   = (const float*)d_in[9];
    const float* u3   = (const float*)d_in[10];
    const int*   eidx = (const int*)d_in[11];
    const float* W1   = (const float*)d_in[12];
    const float* b1   = (const float*)d_in[13];
    const float* W2   = (const float*)d_in[14];
    const float* b2   = (const float*)d_in[15];
    const float* Wr   = (const float*)d_in[16];
    const float* br   = (const float*)d_in[17];

    float* out_s = (float*)d_out;
    float* out_v = out_s + (size_t)NN * FD;

    cudaFuncSetAttribute(phi_kernel,  cudaFuncAttributeMaxDynamicSharedMemorySize, PHI_SMEM);
    cudaFuncSetAttribute(edge_kernel, cudaFuncAttributeMaxDynamicSharedMemorySize, EDGE_SMEM);

    cudaMemcpyAsync(out_s, s, (size_t)NN * FD * sizeof(float),     cudaMemcpyDeviceToDevice, 0);
    cudaMemcpyAsync(out_v, v, (size_t)NN * 3 * FD * sizeof(float), cudaMemcpyDeviceToDevice, 0);

    phi_kernel<<<(NN + PHI_BM - 1) / PHI_BM, 256, PHI_SMEM>>>(s, W1, b1, W2, b2);

    edge_kernel<<<EGRID, 512, EDGE_SMEM>>>(re1, re2, re3, fc1, fc2, fc3,
                                           u1, u2, u3, eidx, Wr, br, v,
                                           out_s, out_v);
}